// round 14
// baseline (speedup 1.0000x reference)
#include <cuda_runtime.h>
#include <cuda_bf16.h>
#include <cuda.h>
#include <math.h>
#include <stdint.h>

#if !defined(__CUDA_ARCH__) || defined(__CUDA_ARCH_FEAT_SM103_ALL) || \
    defined(__CUDA_ARCH_FEAT_SM100_ALL) || defined(__CUDA_ARCH_FEAT_SM101_ALL) || \
    defined(__CUDA_ARCH_FEAT_SM110_ALL)
#define HAS_TC 1
#else
#define HAS_TC 0
#endif

#define BB 16
#define TT 2000
#define MM (BB*TT)
#define DENC 512
#define VV 1024
#define EE 256
#define PP 640
#define JJ 640

#define BM 128            // single accumulator block -> 256-col TMEM -> occ 2
#define BK 64
#define NS 2
#define NTHR 256

// ---------------- scratch ----------------
__device__ float g_enc[(size_t)MM * VV];
__device__ float g_pred[(size_t)MM * VV];
__device__ float g_logits[(size_t)MM * VV];
__device__ __nv_bfloat16 g_hsum[(size_t)MM * VV];
__device__ __nv_bfloat16 g_hb1[(size_t)MM * PP];
__device__ __nv_bfloat16 g_hb2[(size_t)MM * PP];
__device__ __nv_bfloat16 g_encbf[(size_t)MM * DENC];
__device__ __nv_bfloat16 g_embbf[(size_t)VV * EE];
__device__ __nv_bfloat16 g_wt[4u * 1024u * 1024u];
__device__ int2  g_ctx[MM];

#define O_ENC 0
#define O_P1  524288
#define O_P2  851968
#define O_PO  1261568
#define O_J1  1916928
#define O_J2  2572288

__device__ __forceinline__ uint32_t smem_u32(const void* p) {
    uint32_t a;
    asm("{ .reg .u64 t; cvta.to.shared.u64 t, %1; cvt.u32.u64 %0, t; }" : "=r"(a) : "l"(p));
    return a;
}
#define SWZ(b) ((b) ^ (((b) >> 3) & 0x70))

#if HAS_TC
__device__ __forceinline__ uint32_t elect1() {
    uint32_t p;
    asm volatile("{\n\t.reg .pred p;\n\telect.sync _|p, 0xFFFFFFFF;\n\tselp.b32 %0, 1, 0, p;\n\t}" : "=r"(p));
    return p;
}
__device__ __forceinline__ uint64_t make_desc(uint32_t addr) {
    return ((uint64_t)((addr >> 4) & 0x3FFF))
         | (1ull << 16) | (64ull << 32) | (1ull << 46) | (2ull << 61);
}
__device__ __forceinline__ void cp16(uint32_t s, const void* g) {
    asm volatile("cp.async.cg.shared.global [%0], [%1], 16;\n" :: "r"(s), "l"(g));
}
#define CP_COMMIT() asm volatile("cp.async.commit_group;\n" ::: "memory")

__device__ __forceinline__ void mbar_init(uint32_t a, uint32_t cnt) {
    asm volatile("mbarrier.init.shared.b64 [%0], %1;" :: "r"(a), "r"(cnt) : "memory");
}
__device__ __forceinline__ void mbar_wait(uint32_t a, uint32_t parity) {
    uint32_t done = 0;
    while (!done) {
        asm volatile("{\n\t.reg .pred p;\n\t"
            "mbarrier.try_wait.parity.acquire.cta.shared::cta.b64 p, [%1], %2, 0x989680;\n\t"
            "selp.b32 %0, 1, 0, p;\n\t}"
            : "=r"(done) : "r"(a), "r"(parity) : "memory");
    }
}
__device__ __forceinline__ void mbar_expect_tx(uint32_t a, uint32_t bytes) {
    asm volatile("mbarrier.arrive.expect_tx.shared.b64 _, [%0], %1;"
                 :: "r"(a), "r"(bytes) : "memory");
}
__device__ __forceinline__ void tma2d(uint32_t dst, const void* map, int x, int y, uint32_t mbar) {
    asm volatile(
        "cp.async.bulk.tensor.2d.shared::cta.global.tile.mbarrier::complete_tx::bytes "
        "[%0], [%1, {%2, %3}], [%4];"
        :: "r"(dst), "l"(map), "r"(x), "r"(y), "r"(mbar) : "memory");
}
__device__ __forceinline__ void tc_alloc(uint32_t slot, uint32_t ncols) {
    asm volatile("tcgen05.alloc.cta_group::1.sync.aligned.shared::cta.b32 [%0], %1;"
                 :: "r"(slot), "r"(ncols) : "memory");
}
__device__ __forceinline__ void tc_dealloc(uint32_t tmem, uint32_t ncols) {
    asm volatile("tcgen05.dealloc.cta_group::1.sync.aligned.b32 %0, %1;" :: "r"(tmem), "r"(ncols));
}
__device__ __forceinline__ void tc_relinq() {
    asm volatile("tcgen05.relinquish_alloc_permit.cta_group::1.sync.aligned;");
}
__device__ __forceinline__ void tc_commit(uint32_t mbar) {
    asm volatile("tcgen05.commit.cta_group::1.mbarrier::arrive::one.shared::cluster.b64 [%0];"
                 :: "r"(mbar) : "memory");
}
__device__ __forceinline__ void mma_bf16_ss(uint32_t d, uint64_t ad, uint64_t bd,
                                            uint32_t idesc, uint32_t en) {
    asm volatile(
        "{\n\t.reg .pred p;\n\tsetp.ne.u32 p, %4, 0;\n\t"
        "tcgen05.mma.cta_group::1.kind::f16 [%0], %1, %2, %3, p;\n\t}"
        :: "r"(d), "l"(ad), "l"(bd), "r"(idesc), "r"(en) : "memory");
}
__device__ __forceinline__ void ldtm32(uint32_t* r, uint32_t a) {
    asm volatile(
        "tcgen05.ld.sync.aligned.32x32b.x32.b32 "
        "{%0, %1, %2, %3, %4, %5, %6, %7, %8, %9, %10, %11, %12, %13, %14, %15, "
        " %16, %17, %18, %19, %20, %21, %22, %23, %24, %25, %26, %27, %28, %29, %30, %31}, [%32];"
        : "=r"(r[0]), "=r"(r[1]), "=r"(r[2]), "=r"(r[3]), "=r"(r[4]), "=r"(r[5]), "=r"(r[6]), "=r"(r[7]),
          "=r"(r[8]), "=r"(r[9]), "=r"(r[10]), "=r"(r[11]), "=r"(r[12]), "=r"(r[13]), "=r"(r[14]), "=r"(r[15]),
          "=r"(r[16]), "=r"(r[17]), "=r"(r[18]), "=r"(r[19]), "=r"(r[20]), "=r"(r[21]), "=r"(r[22]), "=r"(r[23]),
          "=r"(r[24]), "=r"(r[25]), "=r"(r[26]), "=r"(r[27]), "=r"(r[28]), "=r"(r[29]), "=r"(r[30]), "=r"(r[31])
        : "r"(a));
}
#define TC_WAIT_LD()  asm volatile("tcgen05.wait::ld.sync.aligned;" ::: "memory")
#define TC_FENCE_AFTER()  asm volatile("tcgen05.fence::after_thread_sync;" ::: "memory")
#define TC_FENCE_BEFORE() asm volatile("tcgen05.fence::before_thread_sync;" ::: "memory")
#endif  // HAS_TC

// ---------------- fused prep ----------------
__global__ __launch_bounds__(256) void prep_kernel(
    const int* __restrict__ targets, const float* __restrict__ encoder_out,
    const float* __restrict__ emb,
    const float* __restrict__ W0, const float* __restrict__ W1, const float* __restrict__ W2,
    const float* __restrict__ W3, const float* __restrict__ W4, const float* __restrict__ W5,
    __nv_bfloat16* __restrict__ wt, __nv_bfloat16* __restrict__ encbf,
    __nv_bfloat16* __restrict__ embbf,
    const int* __restrict__ flen, float* __restrict__ out_lens)
{
    __shared__ int pmax[2048];
    __shared__ int tot[256];
    __shared__ float tile[32][33];
    const int blk = blockIdx.x;
    const int tid = threadIdx.x;

    if (blk < 16) {
        const int* tg = targets + (size_t)blk * TT;
        int loc[8];
        int run = -1;
        #pragma unroll
        for (int j = 0; j < 8; ++j) {
            int t = tid * 8 + j;
            int p = (t < TT && tg[t] != 0) ? t : -1;
            run = max(run, p);
            loc[j] = run;
        }
        tot[tid] = run;
        __syncthreads();
        if (tid == 0) {
            int r = -1;
            for (int i = 0; i < 256; ++i) { int v = tot[i]; tot[i] = r; r = max(r, v); }
        }
        __syncthreads();
        int off = tot[tid];
        #pragma unroll
        for (int j = 0; j < 8; ++j) pmax[tid * 8 + j] = max(off, loc[j]);
        __syncthreads();
        for (int t = tid; t < TT; t += 256) {
            int p1 = (t >= 1) ? pmax[t - 1] : -1;
            int p2 = (t >= 2) ? pmax[t - 2] : -1;
            g_ctx[(size_t)blk * TT + t] = make_int2(p1 >= 0 ? tg[p1] : 0, p2 >= 0 ? tg[p2] : 0);
        }
    } else if (blk == 16) {
        if (tid < BB) out_lens[tid] = (float)flen[tid];
    } else if (blk < 273) {
        int i = (blk - 17) * 256 + tid;
        float4 v = reinterpret_cast<const float4*>(emb)[i];
        reinterpret_cast<__nv_bfloat162*>(embbf)[i * 2]     = __floats2bfloat162_rn(v.x, v.y);
        reinterpret_cast<__nv_bfloat162*>(embbf)[i * 2 + 1] = __floats2bfloat162_rn(v.z, v.w);
    } else if (blk < 4113) {
        int t = blk - 273;
        int wsel = t / 640, tidx = t % 640;
        const float* W; __nv_bfloat16* Wt; int K, N;
        switch (wsel) {
            case 0:  W = W0; Wt = wt + O_ENC; K = DENC; N = VV; break;
            case 1:  W = W1; Wt = wt + O_P1;  K = DENC; N = PP; break;
            case 2:  W = W2; Wt = wt + O_P2;  K = PP;   N = PP; break;
            case 3:  W = W3; Wt = wt + O_PO;  K = PP;   N = VV; break;
            case 4:  W = W4; Wt = wt + O_J1;  K = VV;   N = JJ; break;
            default: W = W5; Wt = wt + O_J2;  K = JJ;   N = VV; break;
        }
        int tn = N / 32;
        if (tidx < tn * (K / 32)) {
            int n0 = (tidx % tn) * 32, k0 = (tidx / tn) * 32;
            int tx = tid & 31, ty = tid >> 5;
            #pragma unroll
            for (int i = 0; i < 32; i += 8)
                tile[ty + i][tx] = W[(size_t)(k0 + ty + i) * N + n0 + tx];
            __syncthreads();
            #pragma unroll
            for (int i = 0; i < 32; i += 8)
                Wt[(size_t)(n0 + ty + i) * K + k0 + tx] = __float2bfloat16(tile[tx][ty + i]);
        }
    } else {
        int i = (blk - 4113) * 256 + tid;
        float4 v = reinterpret_cast<const float4*>(encoder_out)[i];
        reinterpret_cast<__nv_bfloat162*>(encbf)[i * 2]     = __floats2bfloat162_rn(v.x, v.y);
        reinterpret_cast<__nv_bfloat162*>(encbf)[i * 2 + 1] = __floats2bfloat162_rn(v.z, v.w);
    }
}

// ---------------- TMA GEMM: BM=128, single accumulator block, occ-2 ----------------
// C = act(A @ B^T + bias); A via mapA [K,M], B via mapB [K,N].
// OUTMODE: 0 = fp32 C; 1 = bf16 C; 2 = fp32 C + bf16 Csum = C + Cadd(fp32).
template<int BN, int ACT, int OUTMODE>
__global__ __launch_bounds__(NTHR) void tma_gemm(
    const __grid_constant__ CUtensorMap mapA,
    const __grid_constant__ CUtensorMap mapB,
    const __nv_bfloat16* __restrict__ A, const __nv_bfloat16* __restrict__ Bt,  // fallback only
    const float* __restrict__ bias,
    void* __restrict__ Cv, const float* __restrict__ Cadd, __nv_bfloat16* __restrict__ Csum,
    int K, int ldc, int ncolOff)
{
#if HAS_TC
    extern __shared__ char smem[];
    const uint32_t sbase = smem_u32(smem);
    const int tid = threadIdx.x;
    const int wid = tid >> 5;
    const int lane = tid & 31;
    const int gRow = blockIdx.x * BM;
    const int ncol = ncolOff + blockIdx.y * BN;

    const uint32_t ctrl = sbase;
    const uint32_t mb_full = sbase + 16;          // 2 x 8B
    const uint32_t mb_done = sbase + 48;          // 2 x 8B
    const uint32_t tile0 = (sbase + 1024 + 1023) & ~1023u;
    const int STAGE = (BM + BN) * 128;

    if (wid == 0) tc_alloc(ctrl, BN);
    if (tid == 0) {
        for (int s = 0; s < NS; s++) { mbar_init(mb_full + 8 * s, 1); mbar_init(mb_done + 8 * s, 1); }
    }
    __syncthreads();
    uint32_t tmem;
    asm volatile("ld.shared.b32 %0, [%1];" : "=r"(tmem) : "r"(ctrl));

    const int KT = K / BK;
    const uint32_t idesc = (1u << 4) | (1u << 7) | (1u << 10)
                         | ((uint32_t)(BN / 8) << 17) | (8u << 24);

    if (wid == 0) {
        auto issue_load = [&](int ki) {
            const int s = ki & 1;
            const uint32_t ab = tile0 + s * STAGE;
            const uint32_t bb = ab + BM * 128;
            mbar_expect_tx(mb_full + 8 * s, (uint32_t)STAGE);
            tma2d(ab, (const void*)&mapA, ki * BK, gRow, mb_full + 8 * s);
            tma2d(bb, (const void*)&mapB, ki * BK, ncol, mb_full + 8 * s);
        };
        if (elect1()) { issue_load(0); issue_load(1); }

        for (int i = 0; i < KT; i++) {
            const int s = i & 1;
            mbar_wait(mb_full + 8 * s, (i / 2) & 1);
            if (elect1()) {
                const uint32_t ab = tile0 + s * STAGE;
                const uint32_t bb = ab + BM * 128;
                uint64_t ad = make_desc(ab), bd = make_desc(bb);
                #pragma unroll
                for (int kk = 0; kk < 4; kk++)
                    mma_bf16_ss(tmem, ad + kk * 2, bd + kk * 2, idesc, (i | kk) ? 1u : 0u);
                tc_commit(mb_done + 8 * s);
            }
            if (i + 2 < KT) {
                mbar_wait(mb_done + 8 * s, (i / 2) & 1);  // MMA(i) must release buffer s
                if (elect1()) issue_load(i + 2);
            }
        }
        mbar_wait(mb_done + 8 * ((KT - 1) & 1), ((KT - 1) / 2) & 1);
    }
    __syncthreads();
    TC_FENCE_AFTER();

    // epilogue: 8 warps; col-half = wid>>2, rows via subpartition (wid&3)
    constexpr int NHALF = (BN > 128) ? 2 : 1;
    if (wid < 4 * NHALF) {
        const int half = wid >> 2;
        const int row = gRow + (wid & 3) * 32 + lane;
        const int cbase = half * 128;
        const float* bs = bias + ncol;
        float* crowf = (OUTMODE != 1) ? ((float*)Cv + (size_t)row * ldc + ncol) : nullptr;
        __nv_bfloat16* crowh = (OUTMODE == 1) ? ((__nv_bfloat16*)Cv + (size_t)row * ldc + ncol) : nullptr;
        const float* erow = (OUTMODE == 2) ? (Cadd + (size_t)row * ldc + ncol) : nullptr;
        __nv_bfloat16* srow = (OUTMODE == 2) ? (Csum + (size_t)row * ldc + ncol) : nullptr;
        #pragma unroll
        for (int cc = 0; cc < 128; cc += 32) {
            const int c0 = cbase + cc;
            uint32_t r[32];
            ldtm32(r, tmem + c0);
            TC_WAIT_LD();
            #pragma unroll
            for (int j = 0; j < 32; j += 4) {
                float4 b4 = *reinterpret_cast<const float4*>(bs + c0 + j);
                float4 o;
                o.x = __uint_as_float(r[j + 0]) + b4.x;
                o.y = __uint_as_float(r[j + 1]) + b4.y;
                o.z = __uint_as_float(r[j + 2]) + b4.z;
                o.w = __uint_as_float(r[j + 3]) + b4.w;
                if (ACT) { o.x = tanhf(o.x); o.y = tanhf(o.y); o.z = tanhf(o.z); o.w = tanhf(o.w); }
                if (OUTMODE == 1) {
                    reinterpret_cast<__nv_bfloat162*>(crowh + c0 + j)[0] = __floats2bfloat162_rn(o.x, o.y);
                    reinterpret_cast<__nv_bfloat162*>(crowh + c0 + j)[1] = __floats2bfloat162_rn(o.z, o.w);
                } else {
                    *reinterpret_cast<float4*>(crowf + c0 + j) = o;
                    if (OUTMODE == 2) {
                        float4 e4 = *reinterpret_cast<const float4*>(erow + c0 + j);
                        reinterpret_cast<__nv_bfloat162*>(srow + c0 + j)[0] = __floats2bfloat162_rn(o.x + e4.x, o.y + e4.y);
                        reinterpret_cast<__nv_bfloat162*>(srow + c0 + j)[1] = __floats2bfloat162_rn(o.z + e4.z, o.w + e4.w);
                    }
                }
            }
        }
        TC_FENCE_BEFORE();
    }
    __syncthreads();
    if (wid == 0) {
        tc_relinq();
        tc_dealloc(tmem, BN);
    }
#else
    const int tid = threadIdx.x;
    const int gRow = blockIdx.x * BM;
    const int ncol0 = ncolOff + blockIdx.y * BN;
    for (int idx = tid; idx < BM * BN; idx += NTHR) {
        int r = idx / BN, n = idx % BN;
        int row = gRow + r, col = ncol0 + n;
        float acc = 0.f;
        for (int k = 0; k < K; k++)
            acc += __bfloat162float(A[(size_t)row * K + k]) * __bfloat162float(Bt[(size_t)col * K + k]);
        acc += bias[col];
        if (ACT) acc = tanhf(acc);
        if (OUTMODE == 1) {
            ((__nv_bfloat16*)Cv)[(size_t)row * ldc + col] = __float2bfloat16(acc);
        } else {
            ((float*)Cv)[(size_t)row * ldc + col] = acc;
            if (OUTMODE == 2)
                Csum[(size_t)row * ldc + col] =
                    __float2bfloat16(acc + Cadd[(size_t)row * ldc + col]);
        }
    }
#endif
}

// ---------------- gather GEMM (p1): cp.async, BM=128, occ-2 ----------------
template<int BN, int ACT>
__global__ __launch_bounds__(NTHR) void gather_gemm(
    const __nv_bfloat16* __restrict__ Bt, const float* __restrict__ bias,
    __nv_bfloat16* __restrict__ Ch, int K, int ldc)
{
#if HAS_TC
    extern __shared__ char smem[];
    const uint32_t sbase = smem_u32(smem);
    const int tid = threadIdx.x;
    const int wid = tid >> 5;
    const int lane = tid & 31;
    const int gRow = blockIdx.x * BM;
    const int ncol0 = blockIdx.y * BN;
    const __nv_bfloat16* BtT = Bt + (size_t)ncol0 * K;

    const uint32_t ctrl = sbase;
    const uint32_t mb   = sbase + 16;
    const uint32_t tile0 = (sbase + 1024 + 1023) & ~1023u;
    const int STAGE = (BM + BN) * BK * 2;

    if (wid == 0) tc_alloc(ctrl, BN);
    if (tid == 0) { for (int s = 0; s < NS; s++) mbar_init(mb + 8 * s, 1); }
    __syncthreads();
    uint32_t tmem;
    asm volatile("ld.shared.b32 %0, [%1];" : "=r"(tmem) : "r"(ctrl));

    const int KT = K / BK;

    auto load_stage = [&](int ki, int s) {
        const int k0 = ki * BK;
        const uint32_t ab = tile0 + s * STAGE;
        const uint32_t bb = ab + BM * BK * 2;
        #pragma unroll
        for (int t = 0; t < 4; t++) {                   // A: 1024 cp16
            int q = tid + t * NTHR, r = q >> 3, cv = q & 7;
            int2 cx = g_ctx[gRow + r];
            int idx = (k0 < 256) ? cx.x : cx.y;
            cp16(ab + SWZ(r * 128 + cv * 16),
                 g_embbf + (size_t)idx * EE + ((k0 & 255) + cv * 8));
        }
        #pragma unroll
        for (int t = 0; t < BN / 32; t++) {             // B: BN*8 cp16
            int q = tid + t * NTHR, r = q >> 3, cv = q & 7;
            cp16(bb + SWZ(r * 128 + cv * 16), BtT + (size_t)r * K + (k0 + cv * 8));
        }
    };

    load_stage(0, 0); CP_COMMIT();
    load_stage(1, 1); CP_COMMIT();

    const uint32_t idesc = (1u << 4) | (1u << 7) | (1u << 10)
                         | ((uint32_t)(BN / 8) << 17) | (8u << 24);

    for (int i = 0; i < KT; i++) {
        const int s = i & 1;
        asm volatile("cp.async.wait_group 1;\n" ::: "memory");
        __syncthreads();
        if (wid == 0) {
            asm volatile("fence.proxy.async.shared::cta;" ::: "memory");
            TC_FENCE_AFTER();
            if (elect1()) {
                const uint32_t ab = tile0 + s * STAGE;
                const uint32_t bb = ab + BM * BK * 2;
                uint64_t ad = make_desc(ab), bd = make_desc(bb);
                #pragma unroll
                for (int kk = 0; kk < 4; kk++)
                    mma_bf16_ss(tmem, ad + kk * 2, bd + kk * 2, idesc, (i | kk) ? 1u : 0u);
                tc_commit(mb + 8 * s);
            }
        }
        if (i + 2 < KT) {
            mbar_wait(mb + 8 * s, (i / 2) & 1);         // MMA(i) releases buffer s
            load_stage(i + 2, s);
        }
        CP_COMMIT();
    }
    mbar_wait(mb + 8 * ((KT - 1) & 1), ((KT - 1) / 2) & 1);
    TC_FENCE_AFTER();
    __syncthreads();

    constexpr int NHALF = (BN > 128) ? 2 : 1;
    if (wid < 4 * NHALF) {
        const int half = wid >> 2;
        const int row = gRow + (wid & 3) * 32 + lane;
        const int cbase = half * 128;
        const float* bs = bias + ncol0;
        __nv_bfloat16* crowh = Ch + (size_t)row * ldc + ncol0;
        #pragma unroll
        for (int cc = 0; cc < 128; cc += 32) {
            const int c0 = cbase + cc;
            uint32_t r[32];
            ldtm32(r, tmem + c0);
            TC_WAIT_LD();
            #pragma unroll
            for (int j = 0; j < 32; j += 4) {
                float4 b4 = *reinterpret_cast<const float4*>(bs + c0 + j);
                float4 o;
                o.x = __uint_as_float(r[j + 0]) + b4.x;
                o.y = __uint_as_float(r[j + 1]) + b4.y;
                o.z = __uint_as_float(r[j + 2]) + b4.z;
                o.w = __uint_as_float(r[j + 3]) + b4.w;
                if (ACT) { o.x = tanhf(o.x); o.y = tanhf(o.y); o.z = tanhf(o.z); o.w = tanhf(o.w); }
                reinterpret_cast<__nv_bfloat162*>(crowh + c0 + j)[0] = __floats2bfloat162_rn(o.x, o.y);
                reinterpret_cast<__nv_bfloat162*>(crowh + c0 + j)[1] = __floats2bfloat162_rn(o.z, o.w);
            }
        }
        TC_FENCE_BEFORE();
    }
    __syncthreads();
    if (wid == 0) {
        tc_relinq();
        tc_dealloc(tmem, BN);
    }
#else
    const int tid = threadIdx.x;
    const int gRow = blockIdx.x * BM;
    const int ncol0 = blockIdx.y * BN;
    for (int idx = tid; idx < BM * BN; idx += NTHR) {
        int r = idx / BN, n = idx % BN;
        int row = gRow + r;
        float acc = 0.f;
        int2 cx = g_ctx[row];
        for (int k = 0; k < K; k++) {
            int e = (k < 256) ? cx.x : cx.y;
            acc += __bfloat162float(g_embbf[(size_t)e * EE + (k & 255)])
                 * __bfloat162float(Bt[(size_t)(ncol0 + n) * K + k]);
        }
        acc += bias[ncol0 + n];
        if (ACT) acc = tanhf(acc);
        Ch[(size_t)row * ldc + ncol0 + n] = __float2bfloat16(acc);
    }
#endif
}

// ---------------- warp-per-row log-softmax (3 tensors) ----------------
__global__ __launch_bounds__(256) void logsoftmax3(
    const float* __restrict__ lg, const float* __restrict__ pd,
    const float* __restrict__ en, float* __restrict__ out)
{
    const int wr = threadIdx.x >> 5;
    const int lane = threadIdx.x & 31;
    const int row = blockIdx.x * 8 + wr;
    const float* X; float* Y;
    if (blockIdx.y == 0)      { X = lg; Y = out; }
    else if (blockIdx.y == 1) { X = pd; Y = out + (size_t)MM * VV; }
    else                      { X = en; Y = out + 2 * (size_t)MM * VV; }

    const float4* xr = reinterpret_cast<const float4*>(X + (size_t)row * VV);
    float4* yr = reinterpret_cast<float4*>(Y + (size_t)row * VV);

    float4 v[8];
    #pragma unroll
    for (int j = 0; j < 8; ++j) v[j] = xr[lane + 32 * j];

    float m = -1e30f;
    #pragma unroll
    for (int j = 0; j < 8; ++j)
        m = fmaxf(m, fmaxf(fmaxf(v[j].x, v[j].y), fmaxf(v[j].z, v[j].w)));
    #pragma unroll
    for (int o = 16; o; o >>= 1) m = fmaxf(m, __shfl_xor_sync(0xffffffffu, m, o));

    float s = 0.f;
    #pragma unroll
    for (int j = 0; j < 8; ++j)
        s += expf(v[j].x - m) + expf(v[j].y - m) + expf(v[j].z - m) + expf(v[j].w - m);
    #pragma unroll
    for (int o = 16; o; o >>= 1) s += __shfl_xor_sync(0xffffffffu, s, o);

    float lse = m + logf(s);
    #pragma unroll
    for (int j = 0; j < 8; ++j) {
        float4 y = make_float4(v[j].x - lse, v[j].y - lse, v[j].z - lse, v[j].w - lse);
        yr[lane + 32 * j] = y;
    }
}

// ---------------- host: tensormap helpers ----------------
typedef CUresult (*PFN_encode)(CUtensorMap*, CUtensorMapDataType, cuuint32_t, void*,
    const cuuint64_t*, const cuuint64_t*, const cuuint32_t*, const cuuint32_t*,
    CUtensorMapInterleave, CUtensorMapSwizzle, CUtensorMapL2promotion, CUtensorMapFloatOOBfill);

static PFN_encode get_encode_fn() {
    void* p = nullptr;
    cudaDriverEntryPointQueryResult qr;
    cudaGetDriverEntryPoint("cuTensorMapEncodeTiled", &p, cudaEnableDefault, &qr);
    return (PFN_encode)p;
}

static void make_map(CUtensorMap* m, void* base, uint64_t d0, uint64_t d1,
                     uint32_t b0, uint32_t b1) {
    cuuint64_t dims[2] = {d0, d1};
    cuuint64_t strides[1] = {d0 * 2};
    cuuint32_t box[2] = {b0, b1};
    cuuint32_t es[2] = {1, 1};
    get_encode_fn()(m, CU_TENSOR_MAP_DATA_TYPE_BFLOAT16, 2, base, dims, strides, box, es,
                    CU_TENSOR_MAP_INTERLEAVE_NONE, CU_TENSOR_MAP_SWIZZLE_128B,
                    CU_TENSOR_MAP_L2_PROMOTION_L2_128B, CU_TENSOR_MAP_FLOAT_OOB_FILL_NONE);
}

// ---------------- launch ----------------
extern "C" void kernel_launch(void* const* d_in, const int* in_sizes, int n_in,
                              void* d_out, int out_size)
{
    const float* encoder_out  = (const float*)d_in[0];
    const int*   features_len = (const int*)  d_in[1];
    const int*   targets      = (const int*)  d_in[2];
    const float* W_enc = (const float*)d_in[3];
    const float* b_enc = (const float*)d_in[4];
    const float* emb   = (const float*)d_in[5];
    const float* W_p1  = (const float*)d_in[6];
    const float* b_p1  = (const float*)d_in[7];
    const float* W_p2  = (const float*)d_in[8];
    const float* b_p2  = (const float*)d_in[9];
    const float* W_po  = (const float*)d_in[10];
    const float* b_po  = (const float*)d_in[11];
    const float* W_j1  = (const float*)d_in[12];
    const float* b_j1  = (const float*)d_in[13];
    const float* W_j2  = (const float*)d_in[14];
    const float* b_j2  = (const float*)d_in[15];

    float *enc, *pred, *logits;
    __nv_bfloat16 *hsum, *hb1, *hb2, *encbf, *embbf, *wt;
    cudaGetSymbolAddress((void**)&enc,    g_enc);
    cudaGetSymbolAddress((void**)&pred,   g_pred);
    cudaGetSymbolAddress((void**)&logits, g_logits);
    cudaGetSymbolAddress((void**)&hsum,   g_hsum);
    cudaGetSymbolAddress((void**)&hb1,    g_hb1);
    cudaGetSymbolAddress((void**)&hb2,    g_hb2);
    cudaGetSymbolAddress((void**)&encbf,  g_encbf);
    cudaGetSymbolAddress((void**)&embbf,  g_embbf);
    cudaGetSymbolAddress((void**)&wt,     g_wt);

    float* out = (float*)d_out;
    float* out_lens = out + 3 * (size_t)MM * VV;

    CUtensorMap mAenc, mAhb1, mAhb2, mAhsum;
    CUtensorMap mBenc, mBp2, mBp2t, mBpo, mBj1, mBj1t, mBj2;
    make_map(&mAenc,  encbf,       512,  32000, 64, 128);
    make_map(&mAhb1,  hb1,         640,  32000, 64, 128);
    make_map(&mAhb2,  hb2,         640,  32000, 64, 128);
    make_map(&mAhsum, hsum,        1024, 32000, 64, 128);
    make_map(&mBenc,  wt + O_ENC,  512,  1024, 64, 256);
    make_map(&mBp2,   wt + O_P2,   640,  640,  64, 256);
    make_map(&mBp2t,  wt + O_P2,   640,  640,  64, 128);
    make_map(&mBpo,   wt + O_PO,   640,  1024, 64, 256);
    make_map(&mBj1,   wt + O_J1,   1024, 640,  64, 256);
    make_map(&mBj1t,  wt + O_J1,   1024, 640,  64, 128);
    make_map(&mBj2,   wt + O_J2,   640,  1024, 64, 256);

    const int TS256 = 2048 + NS * (BM + 256) * 128;   // 100352 -> occ 2
    const int TS128 = 2048 + NS * (BM + 128) * 128;   // 67584  -> occ 3 (TMEM caps at 2... occ 2+)
    cudaFuncSetAttribute(tma_gemm<256,0,0>, cudaFuncAttributeMaxDynamicSharedMemorySize, TS256);
    cudaFuncSetAttribute(tma_gemm<256,1,1>, cudaFuncAttributeMaxDynamicSharedMemorySize, TS256);
    cudaFuncSetAttribute(tma_gemm<256,0,2>, cudaFuncAttributeMaxDynamicSharedMemorySize, TS256);
    cudaFuncSetAttribute(tma_gemm<128,1,1>, cudaFuncAttributeMaxDynamicSharedMemorySize, TS128);
    cudaFuncSetAttribute(gather_gemm<256,1>, cudaFuncAttributeMaxDynamicSharedMemorySize, TS256);
    cudaFuncSetAttribute(gather_gemm<128,1>, cudaFuncAttributeMaxDynamicSharedMemorySize, TS128);

    const int MT = MM / BM;  // 250

    // R11 footprint: 1 stream + 2 events (guard-safe)
    cudaStream_t s2;
    cudaStreamCreateWithFlags(&s2, cudaStreamNonBlocking);
    cudaEvent_t evA, evB;
    cudaEventCreateWithFlags(&evA, cudaEventDisableTiming);
    cudaEventCreateWithFlags(&evB, cudaEventDisableTiming);

    // 1: prep (default stream)
    prep_kernel<<<20113, 256>>>(targets, encoder_out, emb,
        W_enc, W_p1, W_p2, W_po, W_j1, W_j2, wt, encbf, embbf, features_len, out_lens);
    cudaEventRecord(evA, 0);
    cudaStreamWaitEvent(s2, evA, 0);

    // 2-3 (s2): a1 = tanh(gather @ W_p1)  (bf16)
    gather_gemm<128,1><<<dim3(MT, 1), NTHR, TS128, s2>>>(
        wt + O_P1 + (size_t)512 * DENC, b_p1 + 512, hb1 + 512, DENC, PP);
    gather_gemm<256,1><<<dim3(MT, 2), NTHR, TS256, s2>>>(
        wt + O_P1, b_p1, hb1, DENC, PP);

    // 4 (default, ncu capture target): enc (fp32)
    tma_gemm<256,0,0><<<dim3(MT, 4), NTHR, TS256>>>(
        mAenc, mBenc, encbf, wt + O_ENC, b_enc, enc, nullptr, nullptr, DENC, VV, 0);

    // 5-6 (s2): a2 = tanh(a1 @ W_p2)  (bf16)
    tma_gemm<128,1,1><<<dim3(MT, 1), NTHR, TS128, s2>>>(
        mAhb1, mBp2t, hb1, wt + O_P2, b_p2, hb2, nullptr, nullptr, PP, PP, 512);
    tma_gemm<256,1,1><<<dim3(MT, 2), NTHR, TS256, s2>>>(
        mAhb1, mBp2, hb1, wt + O_P2, b_p2, hb2, nullptr, nullptr, PP, PP, 0);
    cudaEventRecord(evB, s2);
    cudaStreamWaitEvent(0, evB, 0);

    // 7: pred (fp32) + hsum = bf16(pred + enc)
    tma_gemm<256,0,2><<<dim3(MT, 4), NTHR, TS256>>>(
        mAhb2, mBpo, hb2, wt + O_PO, b_po, pred, enc, hsum, PP, VV, 0);

    // 8-9: h = tanh(hsum @ W_j1)  (bf16)
    tma_gemm<128,1,1><<<dim3(MT, 1), NTHR, TS128>>>(
        mAhsum, mBj1t, hsum, wt + O_J1, b_j1, hb1, nullptr, nullptr, VV, JJ, 512);
    tma_gemm<256,1,1><<<dim3(MT, 2), NTHR, TS256>>>(
        mAhsum, mBj1, hsum, wt + O_J1, b_j1, hb1, nullptr, nullptr, VV, JJ, 0);

    // 10: logits (fp32)
    tma_gemm<256,0,0><<<dim3(MT, 4), NTHR, TS256>>>(
        mAhb1, mBj2, hb1, wt + O_J2, b_j2, logits, nullptr, nullptr, JJ, VV, 0);

    // 11: warp-per-row log-softmaxes
    logsoftmax3<<<dim3(MM / 8, 3), 256>>>(logits, pred, enc, out);
}

// round 15
// speedup vs baseline: 1.0429x; 1.0429x over previous
#include <cuda_runtime.h>
#include <cuda_bf16.h>
#include <cuda.h>
#include <math.h>
#include <stdint.h>

#if !defined(__CUDA_ARCH__) || defined(__CUDA_ARCH_FEAT_SM103_ALL) || \
    defined(__CUDA_ARCH_FEAT_SM100_ALL) || defined(__CUDA_ARCH_FEAT_SM101_ALL) || \
    defined(__CUDA_ARCH_FEAT_SM110_ALL)
#define HAS_TC 1
#else
#define HAS_TC 0
#endif

#define BB 16
#define TT 2000
#define MM (BB*TT)
#define DENC 512
#define VV 1024
#define EE 256
#define PP 640
#define JJ 640

#define BM 128            // 256-col TMEM per CTA -> 2 CTAs/SM (with early permit relinquish)
#define BK 64
#define NS 2
#define NTHR 256

// ---------------- scratch ----------------
__device__ float g_enc[(size_t)MM * VV];
__device__ float g_pred[(size_t)MM * VV];
__device__ float g_logits[(size_t)MM * VV];
__device__ __nv_bfloat16 g_hsum[(size_t)MM * VV];
__device__ __nv_bfloat16 g_hb1[(size_t)MM * PP];
__device__ __nv_bfloat16 g_hb2[(size_t)MM * PP];
__device__ __nv_bfloat16 g_encbf[(size_t)MM * DENC];
__device__ __nv_bfloat16 g_embbf[(size_t)VV * EE];
__device__ __nv_bfloat16 g_wt[4u * 1024u * 1024u];
__device__ int2  g_ctx[MM];

#define O_ENC 0
#define O_P1  524288
#define O_P2  851968
#define O_PO  1261568
#define O_J1  1916928
#define O_J2  2572288

__device__ __forceinline__ uint32_t smem_u32(const void* p) {
    uint32_t a;
    asm("{ .reg .u64 t; cvta.to.shared.u64 t, %1; cvt.u32.u64 %0, t; }" : "=r"(a) : "l"(p));
    return a;
}
#define SWZ(b) ((b) ^ (((b) >> 3) & 0x70))

#if HAS_TC
__device__ __forceinline__ uint32_t elect1() {
    uint32_t p;
    asm volatile("{\n\t.reg .pred p;\n\telect.sync _|p, 0xFFFFFFFF;\n\tselp.b32 %0, 1, 0, p;\n\t}" : "=r"(p));
    return p;
}
__device__ __forceinline__ uint64_t make_desc(uint32_t addr) {
    return ((uint64_t)((addr >> 4) & 0x3FFF))
         | (1ull << 16) | (64ull << 32) | (1ull << 46) | (2ull << 61);
}
__device__ __forceinline__ void cp16(uint32_t s, const void* g) {
    asm volatile("cp.async.cg.shared.global [%0], [%1], 16;\n" :: "r"(s), "l"(g));
}
#define CP_COMMIT() asm volatile("cp.async.commit_group;\n" ::: "memory")

__device__ __forceinline__ void mbar_init(uint32_t a, uint32_t cnt) {
    asm volatile("mbarrier.init.shared.b64 [%0], %1;" :: "r"(a), "r"(cnt) : "memory");
}
__device__ __forceinline__ void mbar_wait(uint32_t a, uint32_t parity) {
    uint32_t done = 0;
    while (!done) {
        asm volatile("{\n\t.reg .pred p;\n\t"
            "mbarrier.try_wait.parity.acquire.cta.shared::cta.b64 p, [%1], %2, 0x989680;\n\t"
            "selp.b32 %0, 1, 0, p;\n\t}"
            : "=r"(done) : "r"(a), "r"(parity) : "memory");
    }
}
__device__ __forceinline__ void mbar_expect_tx(uint32_t a, uint32_t bytes) {
    asm volatile("mbarrier.arrive.expect_tx.shared.b64 _, [%0], %1;"
                 :: "r"(a), "r"(bytes) : "memory");
}
__device__ __forceinline__ void tma2d(uint32_t dst, const void* map, int x, int y, uint32_t mbar) {
    asm volatile(
        "cp.async.bulk.tensor.2d.shared::cta.global.tile.mbarrier::complete_tx::bytes "
        "[%0], [%1, {%2, %3}], [%4];"
        :: "r"(dst), "l"(map), "r"(x), "r"(y), "r"(mbar) : "memory");
}
__device__ __forceinline__ void tc_alloc(uint32_t slot, uint32_t ncols) {
    asm volatile("tcgen05.alloc.cta_group::1.sync.aligned.shared::cta.b32 [%0], %1;"
                 :: "r"(slot), "r"(ncols) : "memory");
}
__device__ __forceinline__ void tc_dealloc(uint32_t tmem, uint32_t ncols) {
    asm volatile("tcgen05.dealloc.cta_group::1.sync.aligned.b32 %0, %1;" :: "r"(tmem), "r"(ncols));
}
__device__ __forceinline__ void tc_relinq() {
    asm volatile("tcgen05.relinquish_alloc_permit.cta_group::1.sync.aligned;");
}
__device__ __forceinline__ void tc_commit(uint32_t mbar) {
    asm volatile("tcgen05.commit.cta_group::1.mbarrier::arrive::one.shared::cluster.b64 [%0];"
                 :: "r"(mbar) : "memory");
}
__device__ __forceinline__ void mma_bf16_ss(uint32_t d, uint64_t ad, uint64_t bd,
                                            uint32_t idesc, uint32_t en) {
    asm volatile(
        "{\n\t.reg .pred p;\n\tsetp.ne.u32 p, %4, 0;\n\t"
        "tcgen05.mma.cta_group::1.kind::f16 [%0], %1, %2, %3, p;\n\t}"
        :: "r"(d), "l"(ad), "l"(bd), "r"(idesc), "r"(en) : "memory");
}
__device__ __forceinline__ void ldtm32(uint32_t* r, uint32_t a) {
    asm volatile(
        "tcgen05.ld.sync.aligned.32x32b.x32.b32 "
        "{%0, %1, %2, %3, %4, %5, %6, %7, %8, %9, %10, %11, %12, %13, %14, %15, "
        " %16, %17, %18, %19, %20, %21, %22, %23, %24, %25, %26, %27, %28, %29, %30, %31}, [%32];"
        : "=r"(r[0]), "=r"(r[1]), "=r"(r[2]), "=r"(r[3]), "=r"(r[4]), "=r"(r[5]), "=r"(r[6]), "=r"(r[7]),
          "=r"(r[8]), "=r"(r[9]), "=r"(r[10]), "=r"(r[11]), "=r"(r[12]), "=r"(r[13]), "=r"(r[14]), "=r"(r[15]),
          "=r"(r[16]), "=r"(r[17]), "=r"(r[18]), "=r"(r[19]), "=r"(r[20]), "=r"(r[21]), "=r"(r[22]), "=r"(r[23]),
          "=r"(r[24]), "=r"(r[25]), "=r"(r[26]), "=r"(r[27]), "=r"(r[28]), "=r"(r[29]), "=r"(r[30]), "=r"(r[31])
        : "r"(a));
}
#define TC_WAIT_LD()  asm volatile("tcgen05.wait::ld.sync.aligned;" ::: "memory")
#define TC_FENCE_AFTER()  asm volatile("tcgen05.fence::after_thread_sync;" ::: "memory")
#define TC_FENCE_BEFORE() asm volatile("tcgen05.fence::before_thread_sync;" ::: "memory")
#endif  // HAS_TC

// ---------------- fused prep ----------------
__global__ __launch_bounds__(256) void prep_kernel(
    const int* __restrict__ targets, const float* __restrict__ encoder_out,
    const float* __restrict__ emb,
    const float* __restrict__ W0, const float* __restrict__ W1, const float* __restrict__ W2,
    const float* __restrict__ W3, const float* __restrict__ W4, const float* __restrict__ W5,
    __nv_bfloat16* __restrict__ wt, __nv_bfloat16* __restrict__ encbf,
    __nv_bfloat16* __restrict__ embbf,
    const int* __restrict__ flen, float* __restrict__ out_lens)
{
    __shared__ int pmax[2048];
    __shared__ int tot[256];
    __shared__ float tile[32][33];
    const int blk = blockIdx.x;
    const int tid = threadIdx.x;

    if (blk < 16) {
        const int* tg = targets + (size_t)blk * TT;
        int loc[8];
        int run = -1;
        #pragma unroll
        for (int j = 0; j < 8; ++j) {
            int t = tid * 8 + j;
            int p = (t < TT && tg[t] != 0) ? t : -1;
            run = max(run, p);
            loc[j] = run;
        }
        tot[tid] = run;
        __syncthreads();
        if (tid == 0) {
            int r = -1;
            for (int i = 0; i < 256; ++i) { int v = tot[i]; tot[i] = r; r = max(r, v); }
        }
        __syncthreads();
        int off = tot[tid];
        #pragma unroll
        for (int j = 0; j < 8; ++j) pmax[tid * 8 + j] = max(off, loc[j]);
        __syncthreads();
        for (int t = tid; t < TT; t += 256) {
            int p1 = (t >= 1) ? pmax[t - 1] : -1;
            int p2 = (t >= 2) ? pmax[t - 2] : -1;
            g_ctx[(size_t)blk * TT + t] = make_int2(p1 >= 0 ? tg[p1] : 0, p2 >= 0 ? tg[p2] : 0);
        }
    } else if (blk == 16) {
        if (tid < BB) out_lens[tid] = (float)flen[tid];
    } else if (blk < 273) {
        int i = (blk - 17) * 256 + tid;
        float4 v = reinterpret_cast<const float4*>(emb)[i];
        reinterpret_cast<__nv_bfloat162*>(embbf)[i * 2]     = __floats2bfloat162_rn(v.x, v.y);
        reinterpret_cast<__nv_bfloat162*>(embbf)[i * 2 + 1] = __floats2bfloat162_rn(v.z, v.w);
    } else if (blk < 4113) {
        int t = blk - 273;
        int wsel = t / 640, tidx = t % 640;
        const float* W; __nv_bfloat16* Wt; int K, N;
        switch (wsel) {
            case 0:  W = W0; Wt = wt + O_ENC; K = DENC; N = VV; break;
            case 1:  W = W1; Wt = wt + O_P1;  K = DENC; N = PP; break;
            case 2:  W = W2; Wt = wt + O_P2;  K = PP;   N = PP; break;
            case 3:  W = W3; Wt = wt + O_PO;  K = PP;   N = VV; break;
            case 4:  W = W4; Wt = wt + O_J1;  K = VV;   N = JJ; break;
            default: W = W5; Wt = wt + O_J2;  K = JJ;   N = VV; break;
        }
        int tn = N / 32;
        if (tidx < tn * (K / 32)) {
            int n0 = (tidx % tn) * 32, k0 = (tidx / tn) * 32;
            int tx = tid & 31, ty = tid >> 5;
            #pragma unroll
            for (int i = 0; i < 32; i += 8)
                tile[ty + i][tx] = W[(size_t)(k0 + ty + i) * N + n0 + tx];
            __syncthreads();
            #pragma unroll
            for (int i = 0; i < 32; i += 8)
                Wt[(size_t)(n0 + ty + i) * K + k0 + tx] = __float2bfloat16(tile[tx][ty + i]);
        }
    } else {
        int i = (blk - 4113) * 256 + tid;
        float4 v = reinterpret_cast<const float4*>(encoder_out)[i];
        reinterpret_cast<__nv_bfloat162*>(encbf)[i * 2]     = __floats2bfloat162_rn(v.x, v.y);
        reinterpret_cast<__nv_bfloat162*>(encbf)[i * 2 + 1] = __floats2bfloat162_rn(v.z, v.w);
    }
}

// ---------------- TMA GEMM: BM=128, 256-col TMEM, occ-2 (early permit relinquish) --------
// C = act(A @ B^T + bias); A via mapA [K,M], B via mapB [K,N].
// OUTMODE: 0 = fp32 C; 1 = bf16 C; 2 = fp32 C + bf16 Csum = C + Cadd(fp32).
template<int BN, int ACT, int OUTMODE>
__global__ __launch_bounds__(NTHR) void tma_gemm(
    const __grid_constant__ CUtensorMap mapA,
    const __grid_constant__ CUtensorMap mapB,
    const __nv_bfloat16* __restrict__ A, const __nv_bfloat16* __restrict__ Bt,  // fallback only
    const float* __restrict__ bias,
    void* __restrict__ Cv, const float* __restrict__ Cadd, __nv_bfloat16* __restrict__ Csum,
    int K, int ldc, int ncolOff)
{
#if HAS_TC
    extern __shared__ char smem[];
    const uint32_t sbase = smem_u32(smem);
    const int tid = threadIdx.x;
    const int wid = tid >> 5;
    const int lane = tid & 31;
    const int gRow = blockIdx.x * BM;
    const int ncol = ncolOff + blockIdx.y * BN;

    const uint32_t ctrl = sbase;
    const uint32_t mb_full = sbase + 16;
    const uint32_t mb_done = sbase + 48;
    const uint32_t tile0 = (sbase + 1024 + 1023) & ~1023u;
    const int STAGE = (BM + BN) * 128;

    // KEY FIX: relinquish the alloc permit immediately so the co-resident CTA can alloc.
    if (wid == 0) { tc_alloc(ctrl, BN); tc_relinq(); }
    if (tid == 0) {
        for (int s = 0; s < NS; s++) { mbar_init(mb_full + 8 * s, 1); mbar_init(mb_done + 8 * s, 1); }
    }
    __syncthreads();
    uint32_t tmem;
    asm volatile("ld.shared.b32 %0, [%1];" : "=r"(tmem) : "r"(ctrl));

    const int KT = K / BK;
    const uint32_t idesc = (1u << 4) | (1u << 7) | (1u << 10)
                         | ((uint32_t)(BN / 8) << 17) | (8u << 24);

    if (wid == 0) {
        auto issue_load = [&](int ki) {
            const int s = ki & 1;
            const uint32_t ab = tile0 + s * STAGE;
            const uint32_t bb = ab + BM * 128;
            mbar_expect_tx(mb_full + 8 * s, (uint32_t)STAGE);
            tma2d(ab, (const void*)&mapA, ki * BK, gRow, mb_full + 8 * s);
            tma2d(bb, (const void*)&mapB, ki * BK, ncol, mb_full + 8 * s);
        };
        if (elect1()) { issue_load(0); issue_load(1); }

        for (int i = 0; i < KT; i++) {
            const int s = i & 1;
            mbar_wait(mb_full + 8 * s, (i / 2) & 1);
            if (elect1()) {
                const uint32_t ab = tile0 + s * STAGE;
                const uint32_t bb = ab + BM * 128;
                uint64_t ad = make_desc(ab), bd = make_desc(bb);
                #pragma unroll
                for (int kk = 0; kk < 4; kk++)
                    mma_bf16_ss(tmem, ad + kk * 2, bd + kk * 2, idesc, (i | kk) ? 1u : 0u);
                tc_commit(mb_done + 8 * s);
            }
            if (i + 2 < KT) {
                mbar_wait(mb_done + 8 * s, (i / 2) & 1);  // MMA(i) releases buffer s
                if (elect1()) issue_load(i + 2);
            }
        }
        mbar_wait(mb_done + 8 * ((KT - 1) & 1), ((KT - 1) / 2) & 1);
    }
    __syncthreads();
    TC_FENCE_AFTER();

    // epilogue: col-half = wid>>2, rows via subpartition (wid&3)
    constexpr int NHALF = (BN > 128) ? 2 : 1;
    if (wid < 4 * NHALF) {
        const int half = wid >> 2;
        const int row = gRow + (wid & 3) * 32 + lane;
        const int cbase = half * 128;
        const float* bs = bias + ncol;
        float* crowf = (OUTMODE != 1) ? ((float*)Cv + (size_t)row * ldc + ncol) : nullptr;
        __nv_bfloat16* crowh = (OUTMODE == 1) ? ((__nv_bfloat16*)Cv + (size_t)row * ldc + ncol) : nullptr;
        const float* erow = (OUTMODE == 2) ? (Cadd + (size_t)row * ldc + ncol) : nullptr;
        __nv_bfloat16* srow = (OUTMODE == 2) ? (Csum + (size_t)row * ldc + ncol) : nullptr;
        #pragma unroll
        for (int cc = 0; cc < 128; cc += 32) {
            const int c0 = cbase + cc;
            uint32_t r[32];
            ldtm32(r, tmem + c0);
            TC_WAIT_LD();
            #pragma unroll
            for (int j = 0; j < 32; j += 4) {
                float4 b4 = *reinterpret_cast<const float4*>(bs + c0 + j);
                float4 o;
                o.x = __uint_as_float(r[j + 0]) + b4.x;
                o.y = __uint_as_float(r[j + 1]) + b4.y;
                o.z = __uint_as_float(r[j + 2]) + b4.z;
                o.w = __uint_as_float(r[j + 3]) + b4.w;
                if (ACT) { o.x = tanhf(o.x); o.y = tanhf(o.y); o.z = tanhf(o.z); o.w = tanhf(o.w); }
                if (OUTMODE == 1) {
                    reinterpret_cast<__nv_bfloat162*>(crowh + c0 + j)[0] = __floats2bfloat162_rn(o.x, o.y);
                    reinterpret_cast<__nv_bfloat162*>(crowh + c0 + j)[1] = __floats2bfloat162_rn(o.z, o.w);
                } else {
                    *reinterpret_cast<float4*>(crowf + c0 + j) = o;
                    if (OUTMODE == 2) {
                        float4 e4 = *reinterpret_cast<const float4*>(erow + c0 + j);
                        reinterpret_cast<__nv_bfloat162*>(srow + c0 + j)[0] = __floats2bfloat162_rn(o.x + e4.x, o.y + e4.y);
                        reinterpret_cast<__nv_bfloat162*>(srow + c0 + j)[1] = __floats2bfloat162_rn(o.z + e4.z, o.w + e4.w);
                    }
                }
            }
        }
        TC_FENCE_BEFORE();
    }
    __syncthreads();
    if (wid == 0) tc_dealloc(tmem, BN);
#else
    const int tid = threadIdx.x;
    const int gRow = blockIdx.x * BM;
    const int ncol0 = ncolOff + blockIdx.y * BN;
    for (int idx = tid; idx < BM * BN; idx += NTHR) {
        int r = idx / BN, n = idx % BN;
        int row = gRow + r, col = ncol0 + n;
        float acc = 0.f;
        for (int k = 0; k < K; k++)
            acc += __bfloat162float(A[(size_t)row * K + k]) * __bfloat162float(Bt[(size_t)col * K + k]);
        acc += bias[col];
        if (ACT) acc = tanhf(acc);
        if (OUTMODE == 1) {
            ((__nv_bfloat16*)Cv)[(size_t)row * ldc + col] = __float2bfloat16(acc);
        } else {
            ((float*)Cv)[(size_t)row * ldc + col] = acc;
            if (OUTMODE == 2)
                Csum[(size_t)row * ldc + col] =
                    __float2bfloat16(acc + Cadd[(size_t)row * ldc + col]);
        }
    }
#endif
}

// ---------------- gather GEMM (p1): cp.async, BM=128, occ-2 ----------------
template<int BN, int ACT>
__global__ __launch_bounds__(NTHR) void gather_gemm(
    const __nv_bfloat16* __restrict__ Bt, const float* __restrict__ bias,
    __nv_bfloat16* __restrict__ Ch, int K, int ldc)
{
#if HAS_TC
    extern __shared__ char smem[];
    const uint32_t sbase = smem_u32(smem);
    const int tid = threadIdx.x;
    const int wid = tid >> 5;
    const int lane = tid & 31;
    const int gRow = blockIdx.x * BM;
    const int ncol0 = blockIdx.y * BN;
    const __nv_bfloat16* BtT = Bt + (size_t)ncol0 * K;

    const uint32_t ctrl = sbase;
    const uint32_t mb   = sbase + 16;
    const uint32_t tile0 = (sbase + 1024 + 1023) & ~1023u;
    const int STAGE = (BM + BN) * BK * 2;

    // KEY FIX: early permit relinquish
    if (wid == 0) { tc_alloc(ctrl, BN); tc_relinq(); }
    if (tid == 0) { for (int s = 0; s < NS; s++) mbar_init(mb + 8 * s, 1); }
    __syncthreads();
    uint32_t tmem;
    asm volatile("ld.shared.b32 %0, [%1];" : "=r"(tmem) : "r"(ctrl));

    const int KT = K / BK;

    auto load_stage = [&](int ki, int s) {
        const int k0 = ki * BK;
        const uint32_t ab = tile0 + s * STAGE;
        const uint32_t bb = ab + BM * BK * 2;
        #pragma unroll
        for (int t = 0; t < 4; t++) {
            int q = tid + t * NTHR, r = q >> 3, cv = q & 7;
            int2 cx = g_ctx[gRow + r];
            int idx = (k0 < 256) ? cx.x : cx.y;
            cp16(ab + SWZ(r * 128 + cv * 16),
                 g_embbf + (size_t)idx * EE + ((k0 & 255) + cv * 8));
        }
        #pragma unroll
        for (int t = 0; t < BN / 32; t++) {
            int q = tid + t * NTHR, r = q >> 3, cv = q & 7;
            cp16(bb + SWZ(r * 128 + cv * 16), BtT + (size_t)r * K + (k0 + cv * 8));
        }
    };

    load_stage(0, 0); CP_COMMIT();
    load_stage(1, 1); CP_COMMIT();

    const uint32_t idesc = (1u << 4) | (1u << 7) | (1u << 10)
                         | ((uint32_t)(BN / 8) << 17) | (8u << 24);

    for (int i = 0; i < KT; i++) {
        const int s = i & 1;
        asm volatile("cp.async.wait_group 1;\n" ::: "memory");
        __syncthreads();
        if (wid == 0) {
            asm volatile("fence.proxy.async.shared::cta;" ::: "memory");
            TC_FENCE_AFTER();
            if (elect1()) {
                const uint32_t ab = tile0 + s * STAGE;
                const uint32_t bb = ab + BM * BK * 2;
                uint64_t ad = make_desc(ab), bd = make_desc(bb);
                #pragma unroll
                for (int kk = 0; kk < 4; kk++)
                    mma_bf16_ss(tmem, ad + kk * 2, bd + kk * 2, idesc, (i | kk) ? 1u : 0u);
                tc_commit(mb + 8 * s);
            }
        }
        if (i + 2 < KT) {
            mbar_wait(mb + 8 * s, (i / 2) & 1);
            load_stage(i + 2, s);
        }
        CP_COMMIT();
    }
    mbar_wait(mb + 8 * ((KT - 1) & 1), ((KT - 1) / 2) & 1);
    TC_FENCE_AFTER();
    __syncthreads();

    constexpr int NHALF = (BN > 128) ? 2 : 1;
    if (wid < 4 * NHALF) {
        const int half = wid >> 2;
        const int row = gRow + (wid & 3) * 32 + lane;
        const int cbase = half * 128;
        const float* bs = bias + ncol0;
        __nv_bfloat16* crowh = Ch + (size_t)row * ldc + ncol0;
        #pragma unroll
        for (int cc = 0; cc < 128; cc += 32) {
            const int c0 = cbase + cc;
            uint32_t r[32];
            ldtm32(r, tmem + c0);
            TC_WAIT_LD();
            #pragma unroll
            for (int j = 0; j < 32; j += 4) {
                float4 b4 = *reinterpret_cast<const float4*>(bs + c0 + j);
                float4 o;
                o.x = __uint_as_float(r[j + 0]) + b4.x;
                o.y = __uint_as_float(r[j + 1]) + b4.y;
                o.z = __uint_as_float(r[j + 2]) + b4.z;
                o.w = __uint_as_float(r[j + 3]) + b4.w;
                if (ACT) { o.x = tanhf(o.x); o.y = tanhf(o.y); o.z = tanhf(o.z); o.w = tanhf(o.w); }
                reinterpret_cast<__nv_bfloat162*>(crowh + c0 + j)[0] = __floats2bfloat162_rn(o.x, o.y);
                reinterpret_cast<__nv_bfloat162*>(crowh + c0 + j)[1] = __floats2bfloat162_rn(o.z, o.w);
            }
        }
        TC_FENCE_BEFORE();
    }
    __syncthreads();
    if (wid == 0) tc_dealloc(tmem, BN);
#else
    const int tid = threadIdx.x;
    const int gRow = blockIdx.x * BM;
    const int ncol0 = blockIdx.y * BN;
    for (int idx = tid; idx < BM * BN; idx += NTHR) {
        int r = idx / BN, n = idx % BN;
        int row = gRow + r;
        float acc = 0.f;
        int2 cx = g_ctx[row];
        for (int k = 0; k < K; k++) {
            int e = (k < 256) ? cx.x : cx.y;
            acc += __bfloat162float(g_embbf[(size_t)e * EE + (k & 255)])
                 * __bfloat162float(Bt[(size_t)(ncol0 + n) * K + k]);
        }
        acc += bias[ncol0 + n];
        if (ACT) acc = tanhf(acc);
        Ch[(size_t)row * ldc + ncol0 + n] = __float2bfloat16(acc);
    }
#endif
}

// ---------------- warp-per-row log-softmax (3 tensors) ----------------
__global__ __launch_bounds__(256) void logsoftmax3(
    const float* __restrict__ lg, const float* __restrict__ pd,
    const float* __restrict__ en, float* __restrict__ out)
{
    const int wr = threadIdx.x >> 5;
    const int lane = threadIdx.x & 31;
    const int row = blockIdx.x * 8 + wr;
    const float* X; float* Y;
    if (blockIdx.y == 0)      { X = lg; Y = out; }
    else if (blockIdx.y == 1) { X = pd; Y = out + (size_t)MM * VV; }
    else                      { X = en; Y = out + 2 * (size_t)MM * VV; }

    const float4* xr = reinterpret_cast<const float4*>(X + (size_t)row * VV);
    float4* yr = reinterpret_cast<float4*>(Y + (size_t)row * VV);

    float4 v[8];
    #pragma unroll
    for (int j = 0; j < 8; ++j) v[j] = xr[lane + 32 * j];

    float m = -1e30f;
    #pragma unroll
    for (int j = 0; j < 8; ++j)
        m = fmaxf(m, fmaxf(fmaxf(v[j].x, v[j].y), fmaxf(v[j].z, v[j].w)));
    #pragma unroll
    for (int o = 16; o; o >>= 1) m = fmaxf(m, __shfl_xor_sync(0xffffffffu, m, o));

    float s = 0.f;
    #pragma unroll
    for (int j = 0; j < 8; ++j)
        s += expf(v[j].x - m) + expf(v[j].y - m) + expf(v[j].z - m) + expf(v[j].w - m);
    #pragma unroll
    for (int o = 16; o; o >>= 1) s += __shfl_xor_sync(0xffffffffu, s, o);

    float lse = m + logf(s);
    #pragma unroll
    for (int j = 0; j < 8; ++j) {
        float4 y = make_float4(v[j].x - lse, v[j].y - lse, v[j].z - lse, v[j].w - lse);
        yr[lane + 32 * j] = y;
    }
}

// ---------------- host: tensormap helpers ----------------
typedef CUresult (*PFN_encode)(CUtensorMap*, CUtensorMapDataType, cuuint32_t, void*,
    const cuuint64_t*, const cuuint64_t*, const cuuint32_t*, const cuuint32_t*,
    CUtensorMapInterleave, CUtensorMapSwizzle, CUtensorMapL2promotion, CUtensorMapFloatOOBfill);

static PFN_encode get_encode_fn() {
    void* p = nullptr;
    cudaDriverEntryPointQueryResult qr;
    cudaGetDriverEntryPoint("cuTensorMapEncodeTiled", &p, cudaEnableDefault, &qr);
    return (PFN_encode)p;
}

static void make_map(CUtensorMap* m, void* base, uint64_t d0, uint64_t d1,
                     uint32_t b0, uint32_t b1) {
    cuuint64_t dims[2] = {d0, d1};
    cuuint64_t strides[1] = {d0 * 2};
    cuuint32_t box[2] = {b0, b1};
    cuuint32_t es[2] = {1, 1};
    get_encode_fn()(m, CU_TENSOR_MAP_DATA_TYPE_BFLOAT16, 2, base, dims, strides, box, es,
                    CU_TENSOR_MAP_INTERLEAVE_NONE, CU_TENSOR_MAP_SWIZZLE_128B,
                    CU_TENSOR_MAP_L2_PROMOTION_L2_128B, CU_TENSOR_MAP_FLOAT_OOB_FILL_NONE);
}

// ---------------- launch ----------------
extern "C" void kernel_launch(void* const* d_in, const int* in_sizes, int n_in,
                              void* d_out, int out_size)
{
    const float* encoder_out  = (const float*)d_in[0];
    const int*   features_len = (const int*)  d_in[1];
    const int*   targets      = (const int*)  d_in[2];
    const float* W_enc = (const float*)d_in[3];
    const float* b_enc = (const float*)d_in[4];
    const float* emb   = (const float*)d_in[5];
    const float* W_p1  = (const float*)d_in[6];
    const float* b_p1  = (const float*)d_in[7];
    const float* W_p2  = (const float*)d_in[8];
    const float* b_p2  = (const float*)d_in[9];
    const float* W_po  = (const float*)d_in[10];
    const float* b_po  = (const float*)d_in[11];
    const float* W_j1  = (const float*)d_in[12];
    const float* b_j1  = (const float*)d_in[13];
    const float* W_j2  = (const float*)d_in[14];
    const float* b_j2  = (const float*)d_in[15];

    float *enc, *pred, *logits;
    __nv_bfloat16 *hsum, *hb1, *hb2, *encbf, *embbf, *wt;
    cudaGetSymbolAddress((void**)&enc,    g_enc);
    cudaGetSymbolAddress((void**)&pred,   g_pred);
    cudaGetSymbolAddress((void**)&logits, g_logits);
    cudaGetSymbolAddress((void**)&hsum,   g_hsum);
    cudaGetSymbolAddress((void**)&hb1,    g_hb1);
    cudaGetSymbolAddress((void**)&hb2,    g_hb2);
    cudaGetSymbolAddress((void**)&encbf,  g_encbf);
    cudaGetSymbolAddress((void**)&embbf,  g_embbf);
    cudaGetSymbolAddress((void**)&wt,     g_wt);

    float* out = (float*)d_out;
    float* out_lens = out + 3 * (size_t)MM * VV;

    CUtensorMap mAenc, mAhb1, mAhb2, mAhsum;
    CUtensorMap mBenc, mBp2, mBp2t, mBpo, mBj1, mBj1t, mBj2;
    make_map(&mAenc,  encbf,       512,  32000, 64, 128);
    make_map(&mAhb1,  hb1,         640,  32000, 64, 128);
    make_map(&mAhb2,  hb2,         640,  32000, 64, 128);
    make_map(&mAhsum, hsum,        1024, 32000, 64, 128);
    make_map(&mBenc,  wt + O_ENC,  512,  1024, 64, 256);
    make_map(&mBp2,   wt + O_P2,   640,  640,  64, 256);
    make_map(&mBp2t,  wt + O_P2,   640,  640,  64, 128);
    make_map(&mBpo,   wt + O_PO,   640,  1024, 64, 256);
    make_map(&mBj1,   wt + O_J1,   1024, 640,  64, 256);
    make_map(&mBj1t,  wt + O_J1,   1024, 640,  64, 128);
    make_map(&mBj2,   wt + O_J2,   640,  1024, 64, 256);

    const int TS256 = 2048 + NS * (BM + 256) * 128;   // 100352 -> occ 2
    const int TS128 = 2048 + NS * (BM + 128) * 128;   // 67584
    cudaFuncSetAttribute(tma_gemm<256,0,0>, cudaFuncAttributeMaxDynamicSharedMemorySize, TS256);
    cudaFuncSetAttribute(tma_gemm<256,1,1>, cudaFuncAttributeMaxDynamicSharedMemorySize, TS256);
    cudaFuncSetAttribute(tma_gemm<256,0,2>, cudaFuncAttributeMaxDynamicSharedMemorySize, TS256);
    cudaFuncSetAttribute(tma_gemm<128,1,1>, cudaFuncAttributeMaxDynamicSharedMemorySize, TS128);
    cudaFuncSetAttribute(gather_gemm<256,1>, cudaFuncAttributeMaxDynamicSharedMemorySize, TS256);
    cudaFuncSetAttribute(gather_gemm<128,1>, cudaFuncAttributeMaxDynamicSharedMemorySize, TS128);

    const int MT = MM / BM;  // 250

    // R11 footprint: 1 stream + 2 events (guard-safe)
    cudaStream_t s2;
    cudaStreamCreateWithFlags(&s2, cudaStreamNonBlocking);
    cudaEvent_t evA, evB;
    cudaEventCreateWithFlags(&evA, cudaEventDisableTiming);
    cudaEventCreateWithFlags(&evB, cudaEventDisableTiming);

    // 1: prep (default stream)
    prep_kernel<<<20113, 256>>>(targets, encoder_out, emb,
        W_enc, W_p1, W_p2, W_po, W_j1, W_j2, wt, encbf, embbf, features_len, out_lens);
    cudaEventRecord(evA, 0);
    cudaStreamWaitEvent(s2, evA, 0);

    // 2-3 (s2): a1 = tanh(gather @ W_p1)  (bf16)
    gather_gemm<128,1><<<dim3(MT, 1), NTHR, TS128, s2>>>(
        wt + O_P1 + (size_t)512 * DENC, b_p1 + 512, hb1 + 512, DENC, PP);
    gather_gemm<256,1><<<dim3(MT, 2), NTHR, TS256, s2>>>(
        wt + O_P1, b_p1, hb1, DENC, PP);

    // 4 (default, ncu capture target): enc (fp32)
    tma_gemm<256,0,0><<<dim3(MT, 4), NTHR, TS256>>>(
        mAenc, mBenc, encbf, wt + O_ENC, b_enc, enc, nullptr, nullptr, DENC, VV, 0);

    // 5-6 (s2): a2 = tanh(a1 @ W_p2)  (bf16)
    tma_gemm<128,1,1><<<dim3(MT, 1), NTHR, TS128, s2>>>(
        mAhb1, mBp2t, hb1, wt + O_P2, b_p2, hb2, nullptr, nullptr, PP, PP, 512);
    tma_gemm<256,1,1><<<dim3(MT, 2), NTHR, TS256, s2>>>(
        mAhb1, mBp2, hb1, wt + O_P2, b_p2, hb2, nullptr, nullptr, PP, PP, 0);
    cudaEventRecord(evB, s2);
    cudaStreamWaitEvent(0, evB, 0);

    // 7: pred (fp32) + hsum = bf16(pred + enc)
    tma_gemm<256,0,2><<<dim3(MT, 4), NTHR, TS256>>>(
        mAhb2, mBpo, hb2, wt + O_PO, b_po, pred, enc, hsum, PP, VV, 0);

    // 8-9: h = tanh(hsum @ W_j1)  (bf16)
    tma_gemm<128,1,1><<<dim3(MT, 1), NTHR, TS128>>>(
        mAhsum, mBj1t, hsum, wt + O_J1, b_j1, hb1, nullptr, nullptr, VV, JJ, 512);
    tma_gemm<256,1,1><<<dim3(MT, 2), NTHR, TS256>>>(
        mAhsum, mBj1, hsum, wt + O_J1, b_j1, hb1, nullptr, nullptr, VV, JJ, 0);

    // 10: logits (fp32)
    tma_gemm<256,0,0><<<dim3(MT, 4), NTHR, TS256>>>(
        mAhb1, mBj2, hb1, wt + O_J2, b_j2, logits, nullptr, nullptr, JJ, VV, 0);

    // 11: warp-per-row log-softmaxes
    logsoftmax3<<<dim3(MM / 8, 3), 256>>>(logits, pred, enc, out);
}

// round 16
// speedup vs baseline: 1.1426x; 1.0956x over previous
#include <cuda_runtime.h>
#include <cuda_bf16.h>
#include <cuda.h>
#include <math.h>
#include <stdint.h>

#if !defined(__CUDA_ARCH__) || defined(__CUDA_ARCH_FEAT_SM103_ALL) || \
    defined(__CUDA_ARCH_FEAT_SM100_ALL) || defined(__CUDA_ARCH_FEAT_SM101_ALL) || \
    defined(__CUDA_ARCH_FEAT_SM110_ALL)
#define HAS_TC 1
#else
#define HAS_TC 0
#endif

#define BB 16
#define TT 2000
#define MM (BB*TT)
#define DENC 512
#define VV 1024
#define EE 256
#define PP 640
#define JJ 640

#define BM 256
#define BK 64
#define NS 3
#define NTHR 512

// ---------------- scratch ----------------
__device__ float g_enc[(size_t)MM * VV];
__device__ float g_pred[(size_t)MM * VV];
__device__ float g_logits[(size_t)MM * VV];
__device__ __nv_bfloat16 g_hsum[(size_t)MM * VV];
__device__ __nv_bfloat16 g_hb1[(size_t)MM * PP];
__device__ __nv_bfloat16 g_hb2[(size_t)MM * PP];
__device__ __nv_bfloat16 g_encbf[(size_t)MM * DENC];
__device__ __nv_bfloat16 g_embbf[(size_t)VV * EE];
__device__ __nv_bfloat16 g_wt[4u * 1024u * 1024u];
__device__ int2  g_ctx[MM];

#define O_ENC 0
#define O_P1  524288
#define O_P2  851968
#define O_PO  1261568
#define O_J1  1916928
#define O_J2  2572288

__device__ __forceinline__ uint32_t smem_u32(const void* p) {
    uint32_t a;
    asm("{ .reg .u64 t; cvta.to.shared.u64 t, %1; cvt.u32.u64 %0, t; }" : "=r"(a) : "l"(p));
    return a;
}
#define SWZ(b) ((b) ^ (((b) >> 3) & 0x70))

#if HAS_TC
__device__ __forceinline__ uint32_t elect1() {
    uint32_t p;
    asm volatile("{\n\t.reg .pred p;\n\telect.sync _|p, 0xFFFFFFFF;\n\tselp.b32 %0, 1, 0, p;\n\t}" : "=r"(p));
    return p;
}
__device__ __forceinline__ uint64_t make_desc(uint32_t addr) {
    return ((uint64_t)((addr >> 4) & 0x3FFF))
         | (1ull << 16) | (64ull << 32) | (1ull << 46) | (2ull << 61);
}
__device__ __forceinline__ void cp16(uint32_t s, const void* g) {
    asm volatile("cp.async.cg.shared.global [%0], [%1], 16;\n" :: "r"(s), "l"(g));
}
#define CP_COMMIT() asm volatile("cp.async.commit_group;\n" ::: "memory")

__device__ __forceinline__ void mbar_init(uint32_t a, uint32_t cnt) {
    asm volatile("mbarrier.init.shared.b64 [%0], %1;" :: "r"(a), "r"(cnt) : "memory");
}
__device__ __forceinline__ void mbar_wait(uint32_t a, uint32_t parity) {
    uint32_t done = 0;
    while (!done) {
        asm volatile("{\n\t.reg .pred p;\n\t"
            "mbarrier.try_wait.parity.acquire.cta.shared::cta.b64 p, [%1], %2, 0x989680;\n\t"
            "selp.b32 %0, 1, 0, p;\n\t}"
            : "=r"(done) : "r"(a), "r"(parity) : "memory");
    }
}
__device__ __forceinline__ void mbar_expect_tx(uint32_t a, uint32_t bytes) {
    asm volatile("mbarrier.arrive.expect_tx.shared.b64 _, [%0], %1;"
                 :: "r"(a), "r"(bytes) : "memory");
}
__device__ __forceinline__ void tma2d(uint32_t dst, const void* map, int x, int y, uint32_t mbar) {
    asm volatile(
        "cp.async.bulk.tensor.2d.shared::cta.global.tile.mbarrier::complete_tx::bytes "
        "[%0], [%1, {%2, %3}], [%4];"
        :: "r"(dst), "l"(map), "r"(x), "r"(y), "r"(mbar) : "memory");
}
__device__ __forceinline__ void tc_alloc(uint32_t slot, uint32_t ncols) {
    asm volatile("tcgen05.alloc.cta_group::1.sync.aligned.shared::cta.b32 [%0], %1;"
                 :: "r"(slot), "r"(ncols) : "memory");
}
__device__ __forceinline__ void tc_dealloc(uint32_t tmem, uint32_t ncols) {
    asm volatile("tcgen05.dealloc.cta_group::1.sync.aligned.b32 %0, %1;" :: "r"(tmem), "r"(ncols));
}
__device__ __forceinline__ void tc_relinq() {
    asm volatile("tcgen05.relinquish_alloc_permit.cta_group::1.sync.aligned;");
}
__device__ __forceinline__ void tc_commit(uint32_t mbar) {
    asm volatile("tcgen05.commit.cta_group::1.mbarrier::arrive::one.shared::cluster.b64 [%0];"
                 :: "r"(mbar) : "memory");
}
__device__ __forceinline__ void mma_bf16_ss(uint32_t d, uint64_t ad, uint64_t bd,
                                            uint32_t idesc, uint32_t en) {
    asm volatile(
        "{\n\t.reg .pred p;\n\tsetp.ne.u32 p, %4, 0;\n\t"
        "tcgen05.mma.cta_group::1.kind::f16 [%0], %1, %2, %3, p;\n\t}"
        :: "r"(d), "l"(ad), "l"(bd), "r"(idesc), "r"(en) : "memory");
}
__device__ __forceinline__ void ldtm32(uint32_t* r, uint32_t a) {
    asm volatile(
        "tcgen05.ld.sync.aligned.32x32b.x32.b32 "
        "{%0, %1, %2, %3, %4, %5, %6, %7, %8, %9, %10, %11, %12, %13, %14, %15, "
        " %16, %17, %18, %19, %20, %21, %22, %23, %24, %25, %26, %27, %28, %29, %30, %31}, [%32];"
        : "=r"(r[0]), "=r"(r[1]), "=r"(r[2]), "=r"(r[3]), "=r"(r[4]), "=r"(r[5]), "=r"(r[6]), "=r"(r[7]),
          "=r"(r[8]), "=r"(r[9]), "=r"(r[10]), "=r"(r[11]), "=r"(r[12]), "=r"(r[13]), "=r"(r[14]), "=r"(r[15]),
          "=r"(r[16]), "=r"(r[17]), "=r"(r[18]), "=r"(r[19]), "=r"(r[20]), "=r"(r[21]), "=r"(r[22]), "=r"(r[23]),
          "=r"(r[24]), "=r"(r[25]), "=r"(r[26]), "=r"(r[27]), "=r"(r[28]), "=r"(r[29]), "=r"(r[30]), "=r"(r[31])
        : "r"(a));
}
#define TC_WAIT_LD()  asm volatile("tcgen05.wait::ld.sync.aligned;" ::: "memory")
#define TC_FENCE_AFTER()  asm volatile("tcgen05.fence::after_thread_sync;" ::: "memory")
#define TC_FENCE_BEFORE() asm volatile("tcgen05.fence::before_thread_sync;" ::: "memory")
#endif  // HAS_TC

// ---------------- prep_small: ctx + lens + f2bf(emb) + transposes ----------------
__global__ __launch_bounds__(256) void prep_small(
    const int* __restrict__ targets, const float* __restrict__ emb,
    const float* __restrict__ W0, const float* __restrict__ W1, const float* __restrict__ W2,
    const float* __restrict__ W3, const float* __restrict__ W4, const float* __restrict__ W5,
    __nv_bfloat16* __restrict__ wt, __nv_bfloat16* __restrict__ embbf,
    const int* __restrict__ flen, float* __restrict__ out_lens)
{
    __shared__ int pmax[2048];
    __shared__ int tot[256];
    __shared__ float tile[32][33];
    const int blk = blockIdx.x;
    const int tid = threadIdx.x;

    if (blk < 16) {
        const int* tg = targets + (size_t)blk * TT;
        int loc[8];
        int run = -1;
        #pragma unroll
        for (int j = 0; j < 8; ++j) {
            int t = tid * 8 + j;
            int p = (t < TT && tg[t] != 0) ? t : -1;
            run = max(run, p);
            loc[j] = run;
        }
        tot[tid] = run;
        __syncthreads();
        if (tid == 0) {
            int r = -1;
            for (int i = 0; i < 256; ++i) { int v = tot[i]; tot[i] = r; r = max(r, v); }
        }
        __syncthreads();
        int off = tot[tid];
        #pragma unroll
        for (int j = 0; j < 8; ++j) pmax[tid * 8 + j] = max(off, loc[j]);
        __syncthreads();
        for (int t = tid; t < TT; t += 256) {
            int p1 = (t >= 1) ? pmax[t - 1] : -1;
            int p2 = (t >= 2) ? pmax[t - 2] : -1;
            g_ctx[(size_t)blk * TT + t] = make_int2(p1 >= 0 ? tg[p1] : 0, p2 >= 0 ? tg[p2] : 0);
        }
    } else if (blk == 16) {
        if (tid < BB) out_lens[tid] = (float)flen[tid];
    } else if (blk < 273) {
        int i = (blk - 17) * 256 + tid;
        float4 v = reinterpret_cast<const float4*>(emb)[i];
        reinterpret_cast<__nv_bfloat162*>(embbf)[i * 2]     = __floats2bfloat162_rn(v.x, v.y);
        reinterpret_cast<__nv_bfloat162*>(embbf)[i * 2 + 1] = __floats2bfloat162_rn(v.z, v.w);
    } else {
        int t = blk - 273;
        int wsel = t / 640, tidx = t % 640;
        const float* W; __nv_bfloat16* Wt; int K, N;
        switch (wsel) {
            case 0:  W = W0; Wt = wt + O_ENC; K = DENC; N = VV; break;
            case 1:  W = W1; Wt = wt + O_P1;  K = DENC; N = PP; break;
            case 2:  W = W2; Wt = wt + O_P2;  K = PP;   N = PP; break;
            case 3:  W = W3; Wt = wt + O_PO;  K = PP;   N = VV; break;
            case 4:  W = W4; Wt = wt + O_J1;  K = VV;   N = JJ; break;
            default: W = W5; Wt = wt + O_J2;  K = JJ;   N = VV; break;
        }
        int tn = N / 32;
        if (tidx < tn * (K / 32)) {
            int n0 = (tidx % tn) * 32, k0 = (tidx / tn) * 32;
            int tx = tid & 31, ty = tid >> 5;
            #pragma unroll
            for (int i = 0; i < 32; i += 8)
                tile[ty + i][tx] = W[(size_t)(k0 + ty + i) * N + n0 + tx];
            __syncthreads();
            #pragma unroll
            for (int i = 0; i < 32; i += 8)
                Wt[(size_t)(n0 + ty + i) * K + k0 + tx] = __float2bfloat16(tile[tx][ty + i]);
        }
    }
}

// ---------------- f2bf for encoder_out ----------------
__global__ __launch_bounds__(256) void f2bf_kernel(
    const float* __restrict__ s, __nv_bfloat16* __restrict__ d)
{
    int i = blockIdx.x * 256 + threadIdx.x;
    float4 v = reinterpret_cast<const float4*>(s)[i];
    reinterpret_cast<__nv_bfloat162*>(d)[i * 2]     = __floats2bfloat162_rn(v.x, v.y);
    reinterpret_cast<__nv_bfloat162*>(d)[i * 2 + 1] = __floats2bfloat162_rn(v.z, v.w);
}

// ---------------- TMA GEMM (R11 core, unchanged) ----------------
template<int BN, int ACT, int OUTMODE>
__global__ __launch_bounds__(NTHR) void tma_gemm(
    const __grid_constant__ CUtensorMap mapA,
    const __grid_constant__ CUtensorMap mapB,
    const __nv_bfloat16* __restrict__ A, const __nv_bfloat16* __restrict__ Bt,  // fallback only
    const float* __restrict__ bias,
    void* __restrict__ Cv, const float* __restrict__ Cadd, __nv_bfloat16* __restrict__ Csum,
    int K, int ldc, int ncolOff)
{
#if HAS_TC
    extern __shared__ char smem[];
    const uint32_t sbase = smem_u32(smem);
    const int tid = threadIdx.x;
    const int wid = tid >> 5;
    const int lane = tid & 31;
    const int gRow = blockIdx.x * BM;
    const int ncol = ncolOff + blockIdx.y * BN;

    const uint32_t ctrl = sbase;
    const uint32_t mb_full = sbase + 16;
    const uint32_t mb_done = sbase + 64;
    const uint32_t tile0 = (sbase + 1024 + 1023) & ~1023u;
    const int STAGE = (BM + BN) * 128;

    if (wid == 0) tc_alloc(ctrl, 512);
    if (tid == 0) {
        for (int s = 0; s < NS; s++) { mbar_init(mb_full + 8 * s, 1); mbar_init(mb_done + 8 * s, 1); }
    }
    __syncthreads();
    uint32_t tmem;
    asm volatile("ld.shared.b32 %0, [%1];" : "=r"(tmem) : "r"(ctrl));

    const int KT = K / BK;
    const uint32_t idesc = (1u << 4) | (1u << 7) | (1u << 10)
                         | ((uint32_t)(BN / 8) << 17) | (8u << 24);

    if (wid == 0) {
        auto issue_load = [&](int ki) {
            const int s = ki % NS;
            const uint32_t ab = tile0 + s * STAGE;
            const uint32_t bb = ab + BM * 128;
            mbar_expect_tx(mb_full + 8 * s, (uint32_t)STAGE);
            tma2d(ab, (const void*)&mapA, ki * BK, gRow, mb_full + 8 * s);
            tma2d(bb, (const void*)&mapB, ki * BK, ncol, mb_full + 8 * s);
        };
        if (elect1()) { issue_load(0); issue_load(1); }

        for (int i = 0; i < KT; i++) {
            const int s = i % NS;
            mbar_wait(mb_full + 8 * s, (i / NS) & 1);
            if (elect1()) {
                const uint32_t ab = tile0 + s * STAGE;
                const uint32_t bb = ab + BM * 128;
                uint64_t bd = make_desc(bb);
                #pragma unroll
                for (int m = 0; m < 2; m++) {
                    uint64_t ad = make_desc(ab + m * (128 * 128));
                    #pragma unroll
                    for (int kk = 0; kk < 4; kk++)
                        mma_bf16_ss(tmem + m * 256, ad + kk * 2, bd + kk * 2, idesc,
                                    (i | kk) ? 1u : 0u);
                }
                tc_commit(mb_done + 8 * s);
            }
            if (i + 2 < KT) {
                if (i >= 1) mbar_wait(mb_done + 8 * ((i - 1) % NS), ((i - 1) / NS) & 1);
                if (elect1()) issue_load(i + 2);
            }
        }
        mbar_wait(mb_done + 8 * ((KT - 1) % NS), ((KT - 1) / NS) & 1);
    }
    __syncthreads();
    TC_FENCE_AFTER();

    if (wid < 8) {
        const int mt = wid >> 2;
        const int row = gRow + mt * 128 + (wid & 3) * 32 + lane;
        const uint32_t tbase = tmem + mt * 256;
        const float* bs = bias + ncol;
        float* crowf = (OUTMODE != 1) ? ((float*)Cv + (size_t)row * ldc + ncol) : nullptr;
        __nv_bfloat16* crowh = (OUTMODE == 1) ? ((__nv_bfloat16*)Cv + (size_t)row * ldc + ncol) : nullptr;
        const float* erow = (OUTMODE == 2) ? (Cadd + (size_t)row * ldc + ncol) : nullptr;
        __nv_bfloat16* srow = (OUTMODE == 2) ? (Csum + (size_t)row * ldc + ncol) : nullptr;
        #pragma unroll
        for (int c0 = 0; c0 < BN; c0 += 32) {
            uint32_t r[32];
            ldtm32(r, tbase + c0);
            TC_WAIT_LD();
            #pragma unroll
            for (int j = 0; j < 32; j += 4) {
                float4 b4 = *reinterpret_cast<const float4*>(bs + c0 + j);
                float4 o;
                o.x = __uint_as_float(r[j + 0]) + b4.x;
                o.y = __uint_as_float(r[j + 1]) + b4.y;
                o.z = __uint_as_float(r[j + 2]) + b4.z;
                o.w = __uint_as_float(r[j + 3]) + b4.w;
                if (ACT) { o.x = tanhf(o.x); o.y = tanhf(o.y); o.z = tanhf(o.z); o.w = tanhf(o.w); }
                if (OUTMODE == 1) {
                    reinterpret_cast<__nv_bfloat162*>(crowh + c0 + j)[0] = __floats2bfloat162_rn(o.x, o.y);
                    reinterpret_cast<__nv_bfloat162*>(crowh + c0 + j)[1] = __floats2bfloat162_rn(o.z, o.w);
                } else {
                    *reinterpret_cast<float4*>(crowf + c0 + j) = o;
                    if (OUTMODE == 2) {
                        float4 e4 = *reinterpret_cast<const float4*>(erow + c0 + j);
                        reinterpret_cast<__nv_bfloat162*>(srow + c0 + j)[0] = __floats2bfloat162_rn(o.x + e4.x, o.y + e4.y);
                        reinterpret_cast<__nv_bfloat162*>(srow + c0 + j)[1] = __floats2bfloat162_rn(o.z + e4.z, o.w + e4.w);
                    }
                }
            }
        }
        TC_FENCE_BEFORE();
    }
    __syncthreads();
    if (wid == 0) {
        tc_relinq();
        tc_dealloc(tmem, 512);
    }
#else
    const int tid = threadIdx.x;
    const int gRow = blockIdx.x * BM;
    const int ncol0 = ncolOff + blockIdx.y * BN;
    for (int idx = tid; idx < BM * BN; idx += NTHR) {
        int r = idx / BN, n = idx % BN;
        int row = gRow + r, col = ncol0 + n;
        float acc = 0.f;
        for (int k = 0; k < K; k++)
            acc += __bfloat162float(A[(size_t)row * K + k]) * __bfloat162float(Bt[(size_t)col * K + k]);
        acc += bias[col];
        if (ACT) acc = tanhf(acc);
        if (OUTMODE == 1) {
            ((__nv_bfloat16*)Cv)[(size_t)row * ldc + col] = __float2bfloat16(acc);
        } else {
            ((float*)Cv)[(size_t)row * ldc + col] = acc;
            if (OUTMODE == 2)
                Csum[(size_t)row * ldc + col] =
                    __float2bfloat16(acc + Cadd[(size_t)row * ldc + col]);
        }
    }
#endif
}

// ---------------- gather GEMM (R11 core, unchanged) ----------------
template<int BN, int ACT>
__global__ __launch_bounds__(NTHR) void gather_gemm(
    const __nv_bfloat16* __restrict__ Bt, const float* __restrict__ bias,
    __nv_bfloat16* __restrict__ Ch, int K, int ldc)
{
#if HAS_TC
    extern __shared__ char smem[];
    const uint32_t sbase = smem_u32(smem);
    const int tid = threadIdx.x;
    const int wid = tid >> 5;
    const int lane = tid & 31;
    const int gRow = blockIdx.x * BM;
    const int ncol0 = blockIdx.y * BN;
    const __nv_bfloat16* BtT = Bt + (size_t)ncol0 * K;

    const uint32_t ctrl = sbase;
    const uint32_t mb   = sbase + 16;
    const uint32_t tile0 = (sbase + 1024 + 1023) & ~1023u;
    const int STAGE = (BM + BN) * BK * 2;

    if (wid == 0) tc_alloc(ctrl, 512);
    if (tid == 0) { for (int s = 0; s < NS; s++) mbar_init(mb + 8 * s, 1); }
    __syncthreads();
    uint32_t tmem;
    asm volatile("ld.shared.b32 %0, [%1];" : "=r"(tmem) : "r"(ctrl));

    const int KT = K / BK;

    auto load_stage = [&](int ki, int s) {
        const int k0 = ki * BK;
        const uint32_t ab = tile0 + s * STAGE;
        const uint32_t bb = ab + BM * BK * 2;
        #pragma unroll
        for (int t = 0; t < 4; t++) {
            int q = tid + t * NTHR, r = q >> 3, cv = q & 7;
            int2 cx = g_ctx[gRow + r];
            int idx = (k0 < 256) ? cx.x : cx.y;
            cp16(ab + SWZ(r * 128 + cv * 16),
                 g_embbf + (size_t)idx * EE + ((k0 & 255) + cv * 8));
        }
        #pragma unroll
        for (int t = 0; t < BN / 64; t++) {
            int q = tid + t * NTHR, r = q >> 3, cv = q & 7;
            cp16(bb + SWZ(r * 128 + cv * 16), BtT + (size_t)r * K + (k0 + cv * 8));
        }
    };

    load_stage(0, 0); CP_COMMIT();
    load_stage(1, 1); CP_COMMIT();

    const uint32_t idesc = (1u << 4) | (1u << 7) | (1u << 10)
                         | ((uint32_t)(BN / 8) << 17) | (8u << 24);

    for (int i = 0; i < KT; i++) {
        const int s = i % NS;
        asm volatile("cp.async.wait_group 1;\n" ::: "memory");
        __syncthreads();
        if (wid == 0) {
            asm volatile("fence.proxy.async.shared::cta;" ::: "memory");
            TC_FENCE_AFTER();
            if (elect1()) {
                const uint32_t ab = tile0 + s * STAGE;
                const uint32_t bb = ab + BM * BK * 2;
                uint64_t bd = make_desc(bb);
                #pragma unroll
                for (int m = 0; m < 2; m++) {
                    uint64_t ad = make_desc(ab + m * (128 * 128));
                    #pragma unroll
                    for (int kk = 0; kk < 4; kk++)
                        mma_bf16_ss(tmem + m * 256, ad + kk * 2, bd + kk * 2, idesc,
                                    (i | kk) ? 1u : 0u);
                }
                tc_commit(mb + 8 * s);
            }
        }
        if (i + 2 < KT) {
            if (i >= 1) mbar_wait(mb + 8 * ((i - 1) % NS), ((i - 1) / NS) & 1);
            load_stage(i + 2, (i + 2) % NS);
        }
        CP_COMMIT();
    }
    mbar_wait(mb + 8 * ((KT - 1) % NS), ((KT - 1) / NS) & 1);
    TC_FENCE_AFTER();
    __syncthreads();

    if (wid < 8) {
        const int mt = wid >> 2;
        const int row = gRow + mt * 128 + (wid & 3) * 32 + lane;
        const uint32_t tbase = tmem + mt * 256;
        const float* bs = bias + ncol0;
        __nv_bfloat16* crowh = Ch + (size_t)row * ldc + ncol0;
        #pragma unroll
        for (int c0 = 0; c0 < BN; c0 += 32) {
            uint32_t r[32];
            ldtm32(r, tbase + c0);
            TC_WAIT_LD();
            #pragma unroll
            for (int j = 0; j < 32; j += 4) {
                float4 b4 = *reinterpret_cast<const float4*>(bs + c0 + j);
                float4 o;
                o.x = __uint_as_float(r[j + 0]) + b4.x;
                o.y = __uint_as_float(r[j + 1]) + b4.y;
                o.z = __uint_as_float(r[j + 2]) + b4.z;
                o.w = __uint_as_float(r[j + 3]) + b4.w;
                if (ACT) { o.x = tanhf(o.x); o.y = tanhf(o.y); o.z = tanhf(o.z); o.w = tanhf(o.w); }
                reinterpret_cast<__nv_bfloat162*>(crowh + c0 + j)[0] = __floats2bfloat162_rn(o.x, o.y);
                reinterpret_cast<__nv_bfloat162*>(crowh + c0 + j)[1] = __floats2bfloat162_rn(o.z, o.w);
            }
        }
        TC_FENCE_BEFORE();
    }
    __syncthreads();
    if (wid == 0) {
        tc_relinq();
        tc_dealloc(tmem, 512);
    }
#else
    const int tid = threadIdx.x;
    const int gRow = blockIdx.x * BM;
    const int ncol0 = blockIdx.y * BN;
    for (int idx = tid; idx < BM * BN; idx += NTHR) {
        int r = idx / BN, n = idx % BN;
        int row = gRow + r;
        float acc = 0.f;
        int2 cx = g_ctx[row];
        for (int k = 0; k < K; k++) {
            int e = (k < 256) ? cx.x : cx.y;
            acc += __bfloat162float(g_embbf[(size_t)e * EE + (k & 255)])
                 * __bfloat162float(Bt[(size_t)(ncol0 + n) * K + k]);
        }
        acc += bias[ncol0 + n];
        if (ACT) acc = tanhf(acc);
        Ch[(size_t)row * ldc + ncol0 + n] = __float2bfloat16(acc);
    }
#endif
}

// ---------------- warp-per-row log-softmax (single tensor) ----------------
__global__ __launch_bounds__(256) void logsoftmax1(
    const float* __restrict__ X, float* __restrict__ Y)
{
    const int wr = threadIdx.x >> 5;
    const int lane = threadIdx.x & 31;
    const int row = blockIdx.x * 8 + wr;

    const float4* xr = reinterpret_cast<const float4*>(X + (size_t)row * VV);
    float4* yr = reinterpret_cast<float4*>(Y + (size_t)row * VV);

    float4 v[8];
    #pragma unroll
    for (int j = 0; j < 8; ++j) v[j] = xr[lane + 32 * j];

    float m = -1e30f;
    #pragma unroll
    for (int j = 0; j < 8; ++j)
        m = fmaxf(m, fmaxf(fmaxf(v[j].x, v[j].y), fmaxf(v[j].z, v[j].w)));
    #pragma unroll
    for (int o = 16; o; o >>= 1) m = fmaxf(m, __shfl_xor_sync(0xffffffffu, m, o));

    float s = 0.f;
    #pragma unroll
    for (int j = 0; j < 8; ++j)
        s += expf(v[j].x - m) + expf(v[j].y - m) + expf(v[j].z - m) + expf(v[j].w - m);
    #pragma unroll
    for (int o = 16; o; o >>= 1) s += __shfl_xor_sync(0xffffffffu, s, o);

    float lse = m + logf(s);
    #pragma unroll
    for (int j = 0; j < 8; ++j) {
        float4 y = make_float4(v[j].x - lse, v[j].y - lse, v[j].z - lse, v[j].w - lse);
        yr[lane + 32 * j] = y;
    }
}

// ---------------- host: tensormap helpers ----------------
typedef CUresult (*PFN_encode)(CUtensorMap*, CUtensorMapDataType, cuuint32_t, void*,
    const cuuint64_t*, const cuuint64_t*, const cuuint32_t*, const cuuint32_t*,
    CUtensorMapInterleave, CUtensorMapSwizzle, CUtensorMapL2promotion, CUtensorMapFloatOOBfill);

static PFN_encode get_encode_fn() {
    void* p = nullptr;
    cudaDriverEntryPointQueryResult qr;
    cudaGetDriverEntryPoint("cuTensorMapEncodeTiled", &p, cudaEnableDefault, &qr);
    return (PFN_encode)p;
}

static void make_map(CUtensorMap* m, void* base, uint64_t d0, uint64_t d1,
                     uint32_t b0, uint32_t b1) {
    cuuint64_t dims[2] = {d0, d1};
    cuuint64_t strides[1] = {d0 * 2};
    cuuint32_t box[2] = {b0, b1};
    cuuint32_t es[2] = {1, 1};
    get_encode_fn()(m, CU_TENSOR_MAP_DATA_TYPE_BFLOAT16, 2, base, dims, strides, box, es,
                    CU_TENSOR_MAP_INTERLEAVE_NONE, CU_TENSOR_MAP_SWIZZLE_128B,
                    CU_TENSOR_MAP_L2_PROMOTION_L2_128B, CU_TENSOR_MAP_FLOAT_OOB_FILL_NONE);
}

// ---------------- launch ----------------
extern "C" void kernel_launch(void* const* d_in, const int* in_sizes, int n_in,
                              void* d_out, int out_size)
{
    const float* encoder_out  = (const float*)d_in[0];
    const int*   features_len = (const int*)  d_in[1];
    const int*   targets      = (const int*)  d_in[2];
    const float* W_enc = (const float*)d_in[3];
    const float* b_enc = (const float*)d_in[4];
    const float* emb   = (const float*)d_in[5];
    const float* W_p1  = (const float*)d_in[6];
    const float* b_p1  = (const float*)d_in[7];
    const float* W_p2  = (const float*)d_in[8];
    const float* b_p2  = (const float*)d_in[9];
    const float* W_po  = (const float*)d_in[10];
    const float* b_po  = (const float*)d_in[11];
    const float* W_j1  = (const float*)d_in[12];
    const float* b_j1  = (const float*)d_in[13];
    const float* W_j2  = (const float*)d_in[14];
    const float* b_j2  = (const float*)d_in[15];

    float *enc, *pred, *logits;
    __nv_bfloat16 *hsum, *hb1, *hb2, *encbf, *embbf, *wt;
    cudaGetSymbolAddress((void**)&enc,    g_enc);
    cudaGetSymbolAddress((void**)&pred,   g_pred);
    cudaGetSymbolAddress((void**)&logits, g_logits);
    cudaGetSymbolAddress((void**)&hsum,   g_hsum);
    cudaGetSymbolAddress((void**)&hb1,    g_hb1);
    cudaGetSymbolAddress((void**)&hb2,    g_hb2);
    cudaGetSymbolAddress((void**)&encbf,  g_encbf);
    cudaGetSymbolAddress((void**)&embbf,  g_embbf);
    cudaGetSymbolAddress((void**)&wt,     g_wt);

    float* out = (float*)d_out;
    float* out_log  = out;
    float* out_pred = out + (size_t)MM * VV;
    float* out_enc  = out + 2 * (size_t)MM * VV;
    float* out_lens = out + 3 * (size_t)MM * VV;

    CUtensorMap mAenc, mAhb1, mAhb2, mAhsum;
    CUtensorMap mBenc, mBp2, mBp2t, mBpo, mBj1, mBj1t, mBj2;
    make_map(&mAenc,  encbf,       512,  32000, 64, 256);
    make_map(&mAhb1,  hb1,         640,  32000, 64, 256);
    make_map(&mAhb2,  hb2,         640,  32000, 64, 256);
    make_map(&mAhsum, hsum,        1024, 32000, 64, 256);
    make_map(&mBenc,  wt + O_ENC,  512,  1024, 64, 256);
    make_map(&mBp2,   wt + O_P2,   640,  640,  64, 256);
    make_map(&mBp2t,  wt + O_P2,   640,  640,  64, 128);
    make_map(&mBpo,   wt + O_PO,   640,  1024, 64, 256);
    make_map(&mBj1,   wt + O_J1,   1024, 640,  64, 256);
    make_map(&mBj1t,  wt + O_J1,   1024, 640,  64, 128);
    make_map(&mBj2,   wt + O_J2,   640,  1024, 64, 256);

    const int TS256 = 2048 + NS * (BM + 256) * 128;
    const int TS128 = 2048 + NS * (BM + 128) * 128;
    cudaFuncSetAttribute(tma_gemm<256,0,0>, cudaFuncAttributeMaxDynamicSharedMemorySize, TS256);
    cudaFuncSetAttribute(tma_gemm<256,1,1>, cudaFuncAttributeMaxDynamicSharedMemorySize, TS256);
    cudaFuncSetAttribute(tma_gemm<256,0,2>, cudaFuncAttributeMaxDynamicSharedMemorySize, TS256);
    cudaFuncSetAttribute(tma_gemm<128,1,1>, cudaFuncAttributeMaxDynamicSharedMemorySize, TS128);
    cudaFuncSetAttribute(gather_gemm<256,1>, cudaFuncAttributeMaxDynamicSharedMemorySize, TS256);
    cudaFuncSetAttribute(gather_gemm<128,1>, cudaFuncAttributeMaxDynamicSharedMemorySize, TS128);

    const int MT = MM / BM;  // 125

    // 1 stream + 4 events (events are device-memory-free; stream footprint proven safe in R11)
    cudaStream_t s2;
    cudaStreamCreateWithFlags(&s2, cudaStreamNonBlocking);
    cudaEvent_t evA, evB, evC, evD;
    cudaEventCreateWithFlags(&evA, cudaEventDisableTiming);
    cudaEventCreateWithFlags(&evB, cudaEventDisableTiming);
    cudaEventCreateWithFlags(&evC, cudaEventDisableTiming);
    cudaEventCreateWithFlags(&evD, cudaEventDisableTiming);

    // 1: prep_small (ctx/emb/transpose/lens) — unblocks gather branch fast
    prep_small<<<4113, 256>>>(targets, emb,
        W_enc, W_p1, W_p2, W_po, W_j1, W_j2, wt, embbf, features_len, out_lens);
    cudaEventRecord(evA, 0);
    cudaStreamWaitEvent(s2, evA, 0);

    // 2 (default): heavy encoder f2bf — concurrent with gather on s2
    f2bf_kernel<<<MM * DENC / 4 / 256, 256>>>(encoder_out, encbf);

    // 3-4 (s2): a1 = tanh(gather @ W_p1)  (bf16)
    gather_gemm<128,1><<<dim3(MT, 1), NTHR, TS128, s2>>>(
        wt + O_P1 + (size_t)512 * DENC, b_p1 + 512, hb1 + 512, DENC, PP);
    gather_gemm<256,1><<<dim3(MT, 2), NTHR, TS256, s2>>>(
        wt + O_P1, b_p1, hb1, DENC, PP);

    // 5 (default): enc (fp32)
    tma_gemm<256,0,0><<<dim3(MT, 4), NTHR, TS256>>>(
        mAenc, mBenc, encbf, wt + O_ENC, b_enc, enc, nullptr, nullptr, DENC, VV, 0);

    // 6-7 (s2): a2 = tanh(a1 @ W_p2)  (bf16)
    tma_gemm<128,1,1><<<dim3(MT, 1), NTHR, TS128, s2>>>(
        mAhb1, mBp2t, hb1, wt + O_P2, b_p2, hb2, nullptr, nullptr, PP, PP, 512);
    tma_gemm<256,1,1><<<dim3(MT, 2), NTHR, TS256, s2>>>(
        mAhb1, mBp2, hb1, wt + O_P2, b_p2, hb2, nullptr, nullptr, PP, PP, 0);
    cudaEventRecord(evB, s2);
    cudaStreamWaitEvent(0, evB, 0);

    // 8 (default): pred (fp32) + hsum = bf16(pred + enc)
    tma_gemm<256,0,2><<<dim3(MT, 4), NTHR, TS256>>>(
        mAhb2, mBpo, hb2, wt + O_PO, b_po, pred, enc, hsum, PP, VV, 0);
    cudaEventRecord(evC, 0);
    cudaStreamWaitEvent(s2, evC, 0);

    // 9-10 (s2): softmax(pred), softmax(enc) — overlapped with j1/j2 on default
    logsoftmax1<<<MM / 8, 256, 0, s2>>>(pred, out_pred);
    logsoftmax1<<<MM / 8, 256, 0, s2>>>(enc,  out_enc);
    cudaEventRecord(evD, s2);

    // 11-12 (default): h = tanh(hsum @ W_j1)  (bf16)
    tma_gemm<128,1,1><<<dim3(MT, 1), NTHR, TS128>>>(
        mAhsum, mBj1t, hsum, wt + O_J1, b_j1, hb1, nullptr, nullptr, VV, JJ, 512);
    tma_gemm<256,1,1><<<dim3(MT, 2), NTHR, TS256>>>(
        mAhsum, mBj1, hsum, wt + O_J1, b_j1, hb1, nullptr, nullptr, VV, JJ, 0);

    // 13 (default): logits (fp32)
    tma_gemm<256,0,0><<<dim3(MT, 4), NTHR, TS256>>>(
        mAhb1, mBj2, hb1, wt + O_J2, b_j2, logits, nullptr, nullptr, JJ, VV, 0);

    // 14 (default): softmax(logits)
    logsoftmax1<<<MM / 8, 256>>>(logits, out_log);

    // join s2 softmaxes
    cudaStreamWaitEvent(0, evD, 0);
}

// round 17
// speedup vs baseline: 1.1615x; 1.0165x over previous
#include <cuda_runtime.h>
#include <cuda_bf16.h>
#include <cuda.h>
#include <math.h>
#include <stdint.h>

#if !defined(__CUDA_ARCH__) || defined(__CUDA_ARCH_FEAT_SM103_ALL) || \
    defined(__CUDA_ARCH_FEAT_SM100_ALL) || defined(__CUDA_ARCH_FEAT_SM101_ALL) || \
    defined(__CUDA_ARCH_FEAT_SM110_ALL)
#define HAS_TC 1
#else
#define HAS_TC 0
#endif

#define BB 16
#define TT 2000
#define MM (BB*TT)
#define DENC 512
#define VV 1024
#define EE 256
#define PP 640
#define JJ 640

#define BM 256
#define BK 64
#define NS 3
#define NTHR 512

// ---------------- scratch ----------------
__device__ float g_enc[(size_t)MM * VV];
__device__ float g_pred[(size_t)MM * VV];
__device__ float g_logits[(size_t)MM * VV];
__device__ __nv_bfloat16 g_hsum[(size_t)MM * VV];
__device__ __nv_bfloat16 g_hb1[(size_t)MM * PP];
__device__ __nv_bfloat16 g_hb2[(size_t)MM * PP];
__device__ __nv_bfloat16 g_encbf[(size_t)MM * DENC];
__device__ __nv_bfloat16 g_embbf[(size_t)VV * EE];
__device__ __nv_bfloat16 g_wt[4u * 1024u * 1024u];
__device__ int2  g_ctx[MM];

#define O_ENC 0
#define O_P1  524288
#define O_P2  851968
#define O_PO  1261568
#define O_J1  1916928
#define O_J2  2572288

__device__ __forceinline__ uint32_t smem_u32(const void* p) {
    uint32_t a;
    asm("{ .reg .u64 t; cvta.to.shared.u64 t, %1; cvt.u32.u64 %0, t; }" : "=r"(a) : "l"(p));
    return a;
}
#define SWZ(b) ((b) ^ (((b) >> 3) & 0x70))

#if HAS_TC
__device__ __forceinline__ uint32_t elect1() {
    uint32_t p;
    asm volatile("{\n\t.reg .pred p;\n\telect.sync _|p, 0xFFFFFFFF;\n\tselp.b32 %0, 1, 0, p;\n\t}" : "=r"(p));
    return p;
}
__device__ __forceinline__ uint64_t make_desc(uint32_t addr) {
    return ((uint64_t)((addr >> 4) & 0x3FFF))
         | (1ull << 16) | (64ull << 32) | (1ull << 46) | (2ull << 61);
}
__device__ __forceinline__ void cp16(uint32_t s, const void* g) {
    asm volatile("cp.async.cg.shared.global [%0], [%1], 16;\n" :: "r"(s), "l"(g));
}
#define CP_COMMIT() asm volatile("cp.async.commit_group;\n" ::: "memory")

__device__ __forceinline__ void mbar_init(uint32_t a, uint32_t cnt) {
    asm volatile("mbarrier.init.shared.b64 [%0], %1;" :: "r"(a), "r"(cnt) : "memory");
}
__device__ __forceinline__ void mbar_wait(uint32_t a, uint32_t parity) {
    uint32_t done = 0;
    while (!done) {
        asm volatile("{\n\t.reg .pred p;\n\t"
            "mbarrier.try_wait.parity.acquire.cta.shared::cta.b64 p, [%1], %2, 0x989680;\n\t"
            "selp.b32 %0, 1, 0, p;\n\t}"
            : "=r"(done) : "r"(a), "r"(parity) : "memory");
    }
}
__device__ __forceinline__ void mbar_expect_tx(uint32_t a, uint32_t bytes) {
    asm volatile("mbarrier.arrive.expect_tx.shared.b64 _, [%0], %1;"
                 :: "r"(a), "r"(bytes) : "memory");
}
__device__ __forceinline__ void tma2d(uint32_t dst, const void* map, int x, int y, uint32_t mbar) {
    asm volatile(
        "cp.async.bulk.tensor.2d.shared::cta.global.tile.mbarrier::complete_tx::bytes "
        "[%0], [%1, {%2, %3}], [%4];"
        :: "r"(dst), "l"(map), "r"(x), "r"(y), "r"(mbar) : "memory");
}
__device__ __forceinline__ void tc_alloc(uint32_t slot, uint32_t ncols) {
    asm volatile("tcgen05.alloc.cta_group::1.sync.aligned.shared::cta.b32 [%0], %1;"
                 :: "r"(slot), "r"(ncols) : "memory");
}
__device__ __forceinline__ void tc_dealloc(uint32_t tmem, uint32_t ncols) {
    asm volatile("tcgen05.dealloc.cta_group::1.sync.aligned.b32 %0, %1;" :: "r"(tmem), "r"(ncols));
}
__device__ __forceinline__ void tc_relinq() {
    asm volatile("tcgen05.relinquish_alloc_permit.cta_group::1.sync.aligned;");
}
__device__ __forceinline__ void tc_commit(uint32_t mbar) {
    asm volatile("tcgen05.commit.cta_group::1.mbarrier::arrive::one.shared::cluster.b64 [%0];"
                 :: "r"(mbar) : "memory");
}
__device__ __forceinline__ void mma_bf16_ss(uint32_t d, uint64_t ad, uint64_t bd,
                                            uint32_t idesc, uint32_t en) {
    asm volatile(
        "{\n\t.reg .pred p;\n\tsetp.ne.u32 p, %4, 0;\n\t"
        "tcgen05.mma.cta_group::1.kind::f16 [%0], %1, %2, %3, p;\n\t}"
        :: "r"(d), "l"(ad), "l"(bd), "r"(idesc), "r"(en) : "memory");
}
__device__ __forceinline__ void ldtm32(uint32_t* r, uint32_t a) {
    asm volatile(
        "tcgen05.ld.sync.aligned.32x32b.x32.b32 "
        "{%0, %1, %2, %3, %4, %5, %6, %7, %8, %9, %10, %11, %12, %13, %14, %15, "
        " %16, %17, %18, %19, %20, %21, %22, %23, %24, %25, %26, %27, %28, %29, %30, %31}, [%32];"
        : "=r"(r[0]), "=r"(r[1]), "=r"(r[2]), "=r"(r[3]), "=r"(r[4]), "=r"(r[5]), "=r"(r[6]), "=r"(r[7]),
          "=r"(r[8]), "=r"(r[9]), "=r"(r[10]), "=r"(r[11]), "=r"(r[12]), "=r"(r[13]), "=r"(r[14]), "=r"(r[15]),
          "=r"(r[16]), "=r"(r[17]), "=r"(r[18]), "=r"(r[19]), "=r"(r[20]), "=r"(r[21]), "=r"(r[22]), "=r"(r[23]),
          "=r"(r[24]), "=r"(r[25]), "=r"(r[26]), "=r"(r[27]), "=r"(r[28]), "=r"(r[29]), "=r"(r[30]), "=r"(r[31])
        : "r"(a));
}
#define TC_WAIT_LD()  asm volatile("tcgen05.wait::ld.sync.aligned;" ::: "memory")
#define TC_FENCE_AFTER()  asm volatile("tcgen05.fence::after_thread_sync;" ::: "memory")
#define TC_FENCE_BEFORE() asm volatile("tcgen05.fence::before_thread_sync;" ::: "memory")
#endif  // HAS_TC

// ---------------- prep_small: ctx + lens + f2bf(emb) + transposes ----------------
__global__ __launch_bounds__(256) void prep_small(
    const int* __restrict__ targets, const float* __restrict__ emb,
    const float* __restrict__ W0, const float* __restrict__ W1, const float* __restrict__ W2,
    const float* __restrict__ W3, const float* __restrict__ W4, const float* __restrict__ W5,
    __nv_bfloat16* __restrict__ wt, __nv_bfloat16* __restrict__ embbf,
    const int* __restrict__ flen, float* __restrict__ out_lens)
{
    __shared__ int pmax[2048];
    __shared__ int tot[256];
    __shared__ float tile[32][33];
    const int blk = blockIdx.x;
    const int tid = threadIdx.x;

    if (blk < 16) {
        const int* tg = targets + (size_t)blk * TT;
        int loc[8];
        int run = -1;
        #pragma unroll
        for (int j = 0; j < 8; ++j) {
            int t = tid * 8 + j;
            int p = (t < TT && tg[t] != 0) ? t : -1;
            run = max(run, p);
            loc[j] = run;
        }
        tot[tid] = run;
        __syncthreads();
        if (tid == 0) {
            int r = -1;
            for (int i = 0; i < 256; ++i) { int v = tot[i]; tot[i] = r; r = max(r, v); }
        }
        __syncthreads();
        int off = tot[tid];
        #pragma unroll
        for (int j = 0; j < 8; ++j) pmax[tid * 8 + j] = max(off, loc[j]);
        __syncthreads();
        for (int t = tid; t < TT; t += 256) {
            int p1 = (t >= 1) ? pmax[t - 1] : -1;
            int p2 = (t >= 2) ? pmax[t - 2] : -1;
            g_ctx[(size_t)blk * TT + t] = make_int2(p1 >= 0 ? tg[p1] : 0, p2 >= 0 ? tg[p2] : 0);
        }
    } else if (blk == 16) {
        if (tid < BB) out_lens[tid] = (float)flen[tid];
    } else if (blk < 273) {
        int i = (blk - 17) * 256 + tid;
        float4 v = reinterpret_cast<const float4*>(emb)[i];
        reinterpret_cast<__nv_bfloat162*>(embbf)[i * 2]     = __floats2bfloat162_rn(v.x, v.y);
        reinterpret_cast<__nv_bfloat162*>(embbf)[i * 2 + 1] = __floats2bfloat162_rn(v.z, v.w);
    } else {
        int t = blk - 273;
        int wsel = t / 640, tidx = t % 640;
        const float* W; __nv_bfloat16* Wt; int K, N;
        switch (wsel) {
            case 0:  W = W0; Wt = wt + O_ENC; K = DENC; N = VV; break;
            case 1:  W = W1; Wt = wt + O_P1;  K = DENC; N = PP; break;
            case 2:  W = W2; Wt = wt + O_P2;  K = PP;   N = PP; break;
            case 3:  W = W3; Wt = wt + O_PO;  K = PP;   N = VV; break;
            case 4:  W = W4; Wt = wt + O_J1;  K = VV;   N = JJ; break;
            default: W = W5; Wt = wt + O_J2;  K = JJ;   N = VV; break;
        }
        int tn = N / 32;
        if (tidx < tn * (K / 32)) {
            int n0 = (tidx % tn) * 32, k0 = (tidx / tn) * 32;
            int tx = tid & 31, ty = tid >> 5;
            #pragma unroll
            for (int i = 0; i < 32; i += 8)
                tile[ty + i][tx] = W[(size_t)(k0 + ty + i) * N + n0 + tx];
            __syncthreads();
            #pragma unroll
            for (int i = 0; i < 32; i += 8)
                Wt[(size_t)(n0 + ty + i) * K + k0 + tx] = __float2bfloat16(tile[tx][ty + i]);
        }
    }
}

// ---------------- f2bf for encoder_out ----------------
__global__ __launch_bounds__(256) void f2bf_kernel(
    const float* __restrict__ s, __nv_bfloat16* __restrict__ d)
{
    int i = blockIdx.x * 256 + threadIdx.x;
    float4 v = __ldcs(reinterpret_cast<const float4*>(s) + i);
    reinterpret_cast<__nv_bfloat162*>(d)[i * 2]     = __floats2bfloat162_rn(v.x, v.y);
    reinterpret_cast<__nv_bfloat162*>(d)[i * 2 + 1] = __floats2bfloat162_rn(v.z, v.w);
}

// ---------------- TMA GEMM (R11 core + streaming stores + rowOff) ----------------
template<int BN, int ACT, int OUTMODE>
__global__ __launch_bounds__(NTHR) void tma_gemm(
    const __grid_constant__ CUtensorMap mapA,
    const __grid_constant__ CUtensorMap mapB,
    const __nv_bfloat16* __restrict__ A, const __nv_bfloat16* __restrict__ Bt,  // fallback only
    const float* __restrict__ bias,
    void* __restrict__ Cv, const float* __restrict__ Cadd, __nv_bfloat16* __restrict__ Csum,
    int K, int ldc, int ncolOff, int rowOff)
{
#if HAS_TC
    extern __shared__ char smem[];
    const uint32_t sbase = smem_u32(smem);
    const int tid = threadIdx.x;
    const int wid = tid >> 5;
    const int lane = tid & 31;
    const int gRow = rowOff + blockIdx.x * BM;
    const int ncol = ncolOff + blockIdx.y * BN;

    const uint32_t ctrl = sbase;
    const uint32_t mb_full = sbase + 16;
    const uint32_t mb_done = sbase + 64;
    const uint32_t tile0 = (sbase + 1024 + 1023) & ~1023u;
    const int STAGE = (BM + BN) * 128;

    if (wid == 0) tc_alloc(ctrl, 512);
    if (tid == 0) {
        for (int s = 0; s < NS; s++) { mbar_init(mb_full + 8 * s, 1); mbar_init(mb_done + 8 * s, 1); }
    }
    __syncthreads();
    uint32_t tmem;
    asm volatile("ld.shared.b32 %0, [%1];" : "=r"(tmem) : "r"(ctrl));

    const int KT = K / BK;
    const uint32_t idesc = (1u << 4) | (1u << 7) | (1u << 10)
                         | ((uint32_t)(BN / 8) << 17) | (8u << 24);

    if (wid == 0) {
        auto issue_load = [&](int ki) {
            const int s = ki % NS;
            const uint32_t ab = tile0 + s * STAGE;
            const uint32_t bb = ab + BM * 128;
            mbar_expect_tx(mb_full + 8 * s, (uint32_t)STAGE);
            tma2d(ab, (const void*)&mapA, ki * BK, gRow, mb_full + 8 * s);
            tma2d(bb, (const void*)&mapB, ki * BK, ncol, mb_full + 8 * s);
        };
        if (elect1()) { issue_load(0); issue_load(1); }

        for (int i = 0; i < KT; i++) {
            const int s = i % NS;
            mbar_wait(mb_full + 8 * s, (i / NS) & 1);
            if (elect1()) {
                const uint32_t ab = tile0 + s * STAGE;
                const uint32_t bb = ab + BM * 128;
                uint64_t bd = make_desc(bb);
                #pragma unroll
                for (int m = 0; m < 2; m++) {
                    uint64_t ad = make_desc(ab + m * (128 * 128));
                    #pragma unroll
                    for (int kk = 0; kk < 4; kk++)
                        mma_bf16_ss(tmem + m * 256, ad + kk * 2, bd + kk * 2, idesc,
                                    (i | kk) ? 1u : 0u);
                }
                tc_commit(mb_done + 8 * s);
            }
            if (i + 2 < KT) {
                if (i >= 1) mbar_wait(mb_done + 8 * ((i - 1) % NS), ((i - 1) / NS) & 1);
                if (elect1()) issue_load(i + 2);
            }
        }
        mbar_wait(mb_done + 8 * ((KT - 1) % NS), ((KT - 1) / NS) & 1);
    }
    __syncthreads();
    TC_FENCE_AFTER();

    if (wid < 8) {
        const int mt = wid >> 2;
        const int row = gRow + mt * 128 + (wid & 3) * 32 + lane;
        const uint32_t tbase = tmem + mt * 256;
        const float* bs = bias + ncol;
        float* crowf = (OUTMODE != 1) ? ((float*)Cv + (size_t)row * ldc + ncol) : nullptr;
        __nv_bfloat16* crowh = (OUTMODE == 1) ? ((__nv_bfloat16*)Cv + (size_t)row * ldc + ncol) : nullptr;
        const float* erow = (OUTMODE == 2) ? (Cadd + (size_t)row * ldc + ncol) : nullptr;
        __nv_bfloat16* srow = (OUTMODE == 2) ? (Csum + (size_t)row * ldc + ncol) : nullptr;
        #pragma unroll
        for (int c0 = 0; c0 < BN; c0 += 32) {
            uint32_t r[32];
            ldtm32(r, tbase + c0);
            TC_WAIT_LD();
            #pragma unroll
            for (int j = 0; j < 32; j += 4) {
                float4 b4 = *reinterpret_cast<const float4*>(bs + c0 + j);
                float4 o;
                o.x = __uint_as_float(r[j + 0]) + b4.x;
                o.y = __uint_as_float(r[j + 1]) + b4.y;
                o.z = __uint_as_float(r[j + 2]) + b4.z;
                o.w = __uint_as_float(r[j + 3]) + b4.w;
                if (ACT) { o.x = tanhf(o.x); o.y = tanhf(o.y); o.z = tanhf(o.z); o.w = tanhf(o.w); }
                if (OUTMODE == 1) {
                    reinterpret_cast<__nv_bfloat162*>(crowh + c0 + j)[0] = __floats2bfloat162_rn(o.x, o.y);
                    reinterpret_cast<__nv_bfloat162*>(crowh + c0 + j)[1] = __floats2bfloat162_rn(o.z, o.w);
                } else {
                    __stcs(reinterpret_cast<float4*>(crowf + c0 + j), o);   // streaming fp32
                    if (OUTMODE == 2) {
                        float4 e4 = __ldcs(reinterpret_cast<const float4*>(erow + c0 + j));
                        reinterpret_cast<__nv_bfloat162*>(srow + c0 + j)[0] = __floats2bfloat162_rn(o.x + e4.x, o.y + e4.y);
                        reinterpret_cast<__nv_bfloat162*>(srow + c0 + j)[1] = __floats2bfloat162_rn(o.z + e4.z, o.w + e4.w);
                    }
                }
            }
        }
        TC_FENCE_BEFORE();
    }
    __syncthreads();
    if (wid == 0) {
        tc_relinq();
        tc_dealloc(tmem, 512);
    }
#else
    const int tid = threadIdx.x;
    const int gRow = rowOff + blockIdx.x * BM;
    const int ncol0 = ncolOff + blockIdx.y * BN;
    for (int idx = tid; idx < BM * BN; idx += NTHR) {
        int r = idx / BN, n = idx % BN;
        int row = gRow + r, col = ncol0 + n;
        float acc = 0.f;
        for (int k = 0; k < K; k++)
            acc += __bfloat162float(A[(size_t)row * K + k]) * __bfloat162float(Bt[(size_t)col * K + k]);
        acc += bias[col];
        if (ACT) acc = tanhf(acc);
        if (OUTMODE == 1) {
            ((__nv_bfloat16*)Cv)[(size_t)row * ldc + col] = __float2bfloat16(acc);
        } else {
            ((float*)Cv)[(size_t)row * ldc + col] = acc;
            if (OUTMODE == 2)
                Csum[(size_t)row * ldc + col] =
                    __float2bfloat16(acc + Cadd[(size_t)row * ldc + col]);
        }
    }
#endif
}

// ---------------- gather GEMM (R11 core, unchanged) ----------------
template<int BN, int ACT>
__global__ __launch_bounds__(NTHR) void gather_gemm(
    const __nv_bfloat16* __restrict__ Bt, const float* __restrict__ bias,
    __nv_bfloat16* __restrict__ Ch, int K, int ldc)
{
#if HAS_TC
    extern __shared__ char smem[];
    const uint32_t sbase = smem_u32(smem);
    const int tid = threadIdx.x;
    const int wid = tid >> 5;
    const int lane = tid & 31;
    const int gRow = blockIdx.x * BM;
    const int ncol0 = blockIdx.y * BN;
    const __nv_bfloat16* BtT = Bt + (size_t)ncol0 * K;

    const uint32_t ctrl = sbase;
    const uint32_t mb   = sbase + 16;
    const uint32_t tile0 = (sbase + 1024 + 1023) & ~1023u;
    const int STAGE = (BM + BN) * BK * 2;

    if (wid == 0) tc_alloc(ctrl, 512);
    if (tid == 0) { for (int s = 0; s < NS; s++) mbar_init(mb + 8 * s, 1); }
    __syncthreads();
    uint32_t tmem;
    asm volatile("ld.shared.b32 %0, [%1];" : "=r"(tmem) : "r"(ctrl));

    const int KT = K / BK;

    auto load_stage = [&](int ki, int s) {
        const int k0 = ki * BK;
        const uint32_t ab = tile0 + s * STAGE;
        const uint32_t bb = ab + BM * BK * 2;
        #pragma unroll
        for (int t = 0; t < 4; t++) {
            int q = tid + t * NTHR, r = q >> 3, cv = q & 7;
            int2 cx = g_ctx[gRow + r];
            int idx = (k0 < 256) ? cx.x : cx.y;
            cp16(ab + SWZ(r * 128 + cv * 16),
                 g_embbf + (size_t)idx * EE + ((k0 & 255) + cv * 8));
        }
        #pragma unroll
        for (int t = 0; t < BN / 64; t++) {
            int q = tid + t * NTHR, r = q >> 3, cv = q & 7;
            cp16(bb + SWZ(r * 128 + cv * 16), BtT + (size_t)r * K + (k0 + cv * 8));
        }
    };

    load_stage(0, 0); CP_COMMIT();
    load_stage(1, 1); CP_COMMIT();

    const uint32_t idesc = (1u << 4) | (1u << 7) | (1u << 10)
                         | ((uint32_t)(BN / 8) << 17) | (8u << 24);

    for (int i = 0; i < KT; i++) {
        const int s = i % NS;
        asm volatile("cp.async.wait_group 1;\n" ::: "memory");
        __syncthreads();
        if (wid == 0) {
            asm volatile("fence.proxy.async.shared::cta;" ::: "memory");
            TC_FENCE_AFTER();
            if (elect1()) {
                const uint32_t ab = tile0 + s * STAGE;
                const uint32_t bb = ab + BM * BK * 2;
                uint64_t bd = make_desc(bb);
                #pragma unroll
                for (int m = 0; m < 2; m++) {
                    uint64_t ad = make_desc(ab + m * (128 * 128));
                    #pragma unroll
                    for (int kk = 0; kk < 4; kk++)
                        mma_bf16_ss(tmem + m * 256, ad + kk * 2, bd + kk * 2, idesc,
                                    (i | kk) ? 1u : 0u);
                }
                tc_commit(mb + 8 * s);
            }
        }
        if (i + 2 < KT) {
            if (i >= 1) mbar_wait(mb + 8 * ((i - 1) % NS), ((i - 1) / NS) & 1);
            load_stage(i + 2, (i + 2) % NS);
        }
        CP_COMMIT();
    }
    mbar_wait(mb + 8 * ((KT - 1) % NS), ((KT - 1) / NS) & 1);
    TC_FENCE_AFTER();
    __syncthreads();

    if (wid < 8) {
        const int mt = wid >> 2;
        const int row = gRow + mt * 128 + (wid & 3) * 32 + lane;
        const uint32_t tbase = tmem + mt * 256;
        const float* bs = bias + ncol0;
        __nv_bfloat16* crowh = Ch + (size_t)row * ldc + ncol0;
        #pragma unroll
        for (int c0 = 0; c0 < BN; c0 += 32) {
            uint32_t r[32];
            ldtm32(r, tbase + c0);
            TC_WAIT_LD();
            #pragma unroll
            for (int j = 0; j < 32; j += 4) {
                float4 b4 = *reinterpret_cast<const float4*>(bs + c0 + j);
                float4 o;
                o.x = __uint_as_float(r[j + 0]) + b4.x;
                o.y = __uint_as_float(r[j + 1]) + b4.y;
                o.z = __uint_as_float(r[j + 2]) + b4.z;
                o.w = __uint_as_float(r[j + 3]) + b4.w;
                if (ACT) { o.x = tanhf(o.x); o.y = tanhf(o.y); o.z = tanhf(o.z); o.w = tanhf(o.w); }
                reinterpret_cast<__nv_bfloat162*>(crowh + c0 + j)[0] = __floats2bfloat162_rn(o.x, o.y);
                reinterpret_cast<__nv_bfloat162*>(crowh + c0 + j)[1] = __floats2bfloat162_rn(o.z, o.w);
            }
        }
        TC_FENCE_BEFORE();
    }
    __syncthreads();
    if (wid == 0) {
        tc_relinq();
        tc_dealloc(tmem, 512);
    }
#else
    const int tid = threadIdx.x;
    const int gRow = blockIdx.x * BM;
    const int ncol0 = blockIdx.y * BN;
    for (int idx = tid; idx < BM * BN; idx += NTHR) {
        int r = idx / BN, n = idx % BN;
        int row = gRow + r;
        float acc = 0.f;
        int2 cx = g_ctx[row];
        for (int k = 0; k < K; k++) {
            int e = (k < 256) ? cx.x : cx.y;
            acc += __bfloat162float(g_embbf[(size_t)e * EE + (k & 255)])
                 * __bfloat162float(Bt[(size_t)(ncol0 + n) * K + k]);
        }
        acc += bias[ncol0 + n];
        if (ACT) acc = tanhf(acc);
        Ch[(size_t)row * ldc + ncol0 + n] = __float2bfloat16(acc);
    }
#endif
}

// ---------------- warp-per-row log-softmax (single tensor, streaming, row-offset) ----
__global__ __launch_bounds__(256) void logsoftmax1(
    const float* __restrict__ X, float* __restrict__ Y, int rowOff)
{
    const int wr = threadIdx.x >> 5;
    const int lane = threadIdx.x & 31;
    const int row = rowOff + blockIdx.x * 8 + wr;

    const float4* xr = reinterpret_cast<const float4*>(X + (size_t)row * VV);
    float4* yr = reinterpret_cast<float4*>(Y + (size_t)row * VV);

    float4 v[8];
    #pragma unroll
    for (int j = 0; j < 8; ++j) v[j] = __ldcs(xr + lane + 32 * j);

    float m = -1e30f;
    #pragma unroll
    for (int j = 0; j < 8; ++j)
        m = fmaxf(m, fmaxf(fmaxf(v[j].x, v[j].y), fmaxf(v[j].z, v[j].w)));
    #pragma unroll
    for (int o = 16; o; o >>= 1) m = fmaxf(m, __shfl_xor_sync(0xffffffffu, m, o));

    float s = 0.f;
    #pragma unroll
    for (int j = 0; j < 8; ++j)
        s += expf(v[j].x - m) + expf(v[j].y - m) + expf(v[j].z - m) + expf(v[j].w - m);
    #pragma unroll
    for (int o = 16; o; o >>= 1) s += __shfl_xor_sync(0xffffffffu, s, o);

    float lse = m + logf(s);
    #pragma unroll
    for (int j = 0; j < 8; ++j) {
        float4 y = make_float4(v[j].x - lse, v[j].y - lse, v[j].z - lse, v[j].w - lse);
        __stcs(yr + lane + 32 * j, y);
    }
}

// ---------------- host: tensormap helpers ----------------
typedef CUresult (*PFN_encode)(CUtensorMap*, CUtensorMapDataType, cuuint32_t, void*,
    const cuuint64_t*, const cuuint64_t*, const cuuint32_t*, const cuuint32_t*,
    CUtensorMapInterleave, CUtensorMapSwizzle, CUtensorMapL2promotion, CUtensorMapFloatOOBfill);

static PFN_encode get_encode_fn() {
    void* p = nullptr;
    cudaDriverEntryPointQueryResult qr;
    cudaGetDriverEntryPoint("cuTensorMapEncodeTiled", &p, cudaEnableDefault, &qr);
    return (PFN_encode)p;
}

static void make_map(CUtensorMap* m, void* base, uint64_t d0, uint64_t d1,
                     uint32_t b0, uint32_t b1) {
    cuuint64_t dims[2] = {d0, d1};
    cuuint64_t strides[1] = {d0 * 2};
    cuuint32_t box[2] = {b0, b1};
    cuuint32_t es[2] = {1, 1};
    get_encode_fn()(m, CU_TENSOR_MAP_DATA_TYPE_BFLOAT16, 2, base, dims, strides, box, es,
                    CU_TENSOR_MAP_INTERLEAVE_NONE, CU_TENSOR_MAP_SWIZZLE_128B,
                    CU_TENSOR_MAP_L2_PROMOTION_L2_128B, CU_TENSOR_MAP_FLOAT_OOB_FILL_NONE);
}

// ---------------- launch ----------------
extern "C" void kernel_launch(void* const* d_in, const int* in_sizes, int n_in,
                              void* d_out, int out_size)
{
    const float* encoder_out  = (const float*)d_in[0];
    const int*   features_len = (const int*)  d_in[1];
    const int*   targets      = (const int*)  d_in[2];
    const float* W_enc = (const float*)d_in[3];
    const float* b_enc = (const float*)d_in[4];
    const float* emb   = (const float*)d_in[5];
    const float* W_p1  = (const float*)d_in[6];
    const float* b_p1  = (const float*)d_in[7];
    const float* W_p2  = (const float*)d_in[8];
    const float* b_p2  = (const float*)d_in[9];
    const float* W_po  = (const float*)d_in[10];
    const float* b_po  = (const float*)d_in[11];
    const float* W_j1  = (const float*)d_in[12];
    const float* b_j1  = (const float*)d_in[13];
    const float* W_j2  = (const float*)d_in[14];
    const float* b_j2  = (const float*)d_in[15];

    float *enc, *pred, *logits;
    __nv_bfloat16 *hsum, *hb1, *hb2, *encbf, *embbf, *wt;
    cudaGetSymbolAddress((void**)&enc,    g_enc);
    cudaGetSymbolAddress((void**)&pred,   g_pred);
    cudaGetSymbolAddress((void**)&logits, g_logits);
    cudaGetSymbolAddress((void**)&hsum,   g_hsum);
    cudaGetSymbolAddress((void**)&hb1,    g_hb1);
    cudaGetSymbolAddress((void**)&hb2,    g_hb2);
    cudaGetSymbolAddress((void**)&encbf,  g_encbf);
    cudaGetSymbolAddress((void**)&embbf,  g_embbf);
    cudaGetSymbolAddress((void**)&wt,     g_wt);

    float* out = (float*)d_out;
    float* out_log  = out;
    float* out_pred = out + (size_t)MM * VV;
    float* out_enc  = out + 2 * (size_t)MM * VV;
    float* out_lens = out + 3 * (size_t)MM * VV;

    CUtensorMap mAenc, mAhb1, mAhb2, mAhsum;
    CUtensorMap mBenc, mBp2, mBp2t, mBpo, mBj1, mBj1t, mBj2;
    make_map(&mAenc,  encbf,       512,  32000, 64, 256);
    make_map(&mAhb1,  hb1,         640,  32000, 64, 256);
    make_map(&mAhb2,  hb2,         640,  32000, 64, 256);
    make_map(&mAhsum, hsum,        1024, 32000, 64, 256);
    make_map(&mBenc,  wt + O_ENC,  512,  1024, 64, 256);
    make_map(&mBp2,   wt + O_P2,   640,  640,  64, 256);
    make_map(&mBp2t,  wt + O_P2,   640,  640,  64, 128);
    make_map(&mBpo,   wt + O_PO,   640,  1024, 64, 256);
    make_map(&mBj1,   wt + O_J1,   1024, 640,  64, 256);
    make_map(&mBj1t,  wt + O_J1,   1024, 640,  64, 128);
    make_map(&mBj2,   wt + O_J2,   640,  1024, 64, 256);

    const int TS256 = 2048 + NS * (BM + 256) * 128;
    const int TS128 = 2048 + NS * (BM + 128) * 128;
    cudaFuncSetAttribute(tma_gemm<256,0,0>, cudaFuncAttributeMaxDynamicSharedMemorySize, TS256);
    cudaFuncSetAttribute(tma_gemm<256,1,1>, cudaFuncAttributeMaxDynamicSharedMemorySize, TS256);
    cudaFuncSetAttribute(tma_gemm<256,0,2>, cudaFuncAttributeMaxDynamicSharedMemorySize, TS256);
    cudaFuncSetAttribute(tma_gemm<128,1,1>, cudaFuncAttributeMaxDynamicSharedMemorySize, TS128);
    cudaFuncSetAttribute(gather_gemm<256,1>, cudaFuncAttributeMaxDynamicSharedMemorySize, TS256);
    cudaFuncSetAttribute(gather_gemm<128,1>, cudaFuncAttributeMaxDynamicSharedMemorySize, TS128);

    const int MT = MM / BM;           // 125
    const int H0 = 63, H1 = 62;       // row-block halves
    const int R1 = H0 * BM;           // 16128

    // 1 stream + 4 events (R16-proven footprint)
    cudaStream_t s2;
    cudaStreamCreateWithFlags(&s2, cudaStreamNonBlocking);
    cudaEvent_t evA, evEnc, evB, evEnd;
    cudaEventCreateWithFlags(&evA,   cudaEventDisableTiming);
    cudaEventCreateWithFlags(&evEnc, cudaEventDisableTiming);
    cudaEventCreateWithFlags(&evB,   cudaEventDisableTiming);
    cudaEventCreateWithFlags(&evEnd, cudaEventDisableTiming);

    // ---- front section ----
    prep_small<<<4113, 256>>>(targets, emb,
        W_enc, W_p1, W_p2, W_po, W_j1, W_j2, wt, embbf, features_len, out_lens);
    cudaEventRecord(evA, 0);
    cudaStreamWaitEvent(s2, evA, 0);

    // default: encoder f2bf + enc GEMM (concurrent with s2 predictor branch)
    f2bf_kernel<<<MM * DENC / 4 / 256, 256>>>(encoder_out, encbf);
    tma_gemm<256,0,0><<<dim3(MT, 4), NTHR, TS256>>>(
        mAenc, mBenc, encbf, wt + O_ENC, b_enc, enc, nullptr, nullptr, DENC, VV, 0, 0);
    cudaEventRecord(evEnc, 0);

    // s2: gather + p2
    gather_gemm<128,1><<<dim3(MT, 1), NTHR, TS128, s2>>>(
        wt + O_P1 + (size_t)512 * DENC, b_p1 + 512, hb1 + 512, DENC, PP);
    gather_gemm<256,1><<<dim3(MT, 2), NTHR, TS256, s2>>>(
        wt + O_P1, b_p1, hb1, DENC, PP);
    tma_gemm<128,1,1><<<dim3(MT, 1), NTHR, TS128, s2>>>(
        mAhb1, mBp2t, hb1, wt + O_P2, b_p2, hb2, nullptr, nullptr, PP, PP, 512, 0);
    tma_gemm<256,1,1><<<dim3(MT, 2), NTHR, TS256, s2>>>(
        mAhb1, mBp2, hb1, wt + O_P2, b_p2, hb2, nullptr, nullptr, PP, PP, 0, 0);
    cudaEventRecord(evB, s2);

    // ---- tail section: 2-way row-split pipeline ----
    // half 0 (rows [0, R1)) on default; half 1 (rows [R1, MM)) on s2
    cudaStreamWaitEvent(0, evB, 0);       // default needs hb2
    cudaStreamWaitEvent(s2, evEnc, 0);    // s2 needs enc (hb2 in-stream)

    // --- half 0 on default ---
    tma_gemm<256,0,2><<<dim3(H0, 4), NTHR, TS256>>>(
        mAhb2, mBpo, hb2, wt + O_PO, b_po, pred, enc, hsum, PP, VV, 0, 0);
    tma_gemm<128,1,1><<<dim3(H0, 1), NTHR, TS128>>>(
        mAhsum, mBj1t, hsum, wt + O_J1, b_j1, hb1, nullptr, nullptr, VV, JJ, 512, 0);
    tma_gemm<256,1,1><<<dim3(H0, 2), NTHR, TS256>>>(
        mAhsum, mBj1, hsum, wt + O_J1, b_j1, hb1, nullptr, nullptr, VV, JJ, 0, 0);
    tma_gemm<256,0,0><<<dim3(H0, 4), NTHR, TS256>>>(
        mAhb1, mBj2, hb1, wt + O_J2, b_j2, logits, nullptr, nullptr, JJ, VV, 0, 0);
    logsoftmax1<<<R1 / 8, 256>>>(logits, out_log, 0);
    logsoftmax1<<<R1 / 8, 256>>>(pred, out_pred, 0);
    logsoftmax1<<<R1 / 8, 256>>>(enc,  out_enc,  0);

    // --- half 1 on s2 ---
    tma_gemm<256,0,2><<<dim3(H1, 4), NTHR, TS256, s2>>>(
        mAhb2, mBpo, hb2, wt + O_PO, b_po, pred, enc, hsum, PP, VV, 0, R1);
    tma_gemm<128,1,1><<<dim3(H1, 1), NTHR, TS128, s2>>>(
        mAhsum, mBj1t, hsum, wt + O_J1, b_j1, hb1, nullptr, nullptr, VV, JJ, 512, R1);
    tma_gemm<256,1,1><<<dim3(H1, 2), NTHR, TS256, s2>>>(
        mAhsum, mBj1, hsum, wt + O_J1, b_j1, hb1, nullptr, nullptr, VV, JJ, 0, R1);
    tma_gemm<256,0,0><<<dim3(H1, 4), NTHR, TS256, s2>>>(
        mAhb1, mBj2, hb1, wt + O_J2, b_j2, logits, nullptr, nullptr, JJ, VV, 0, R1);
    logsoftmax1<<<(MM - R1) / 8, 256, 0, s2>>>(logits, out_log, R1);
    logsoftmax1<<<(MM - R1) / 8, 256, 0, s2>>>(pred, out_pred, R1);
    logsoftmax1<<<(MM - R1) / 8, 256, 0, s2>>>(enc,  out_enc,  R1);
    cudaEventRecord(evEnd, s2);

    // join
    cudaStreamWaitEvent(0, evEnd, 0);
}